// round 6
// baseline (speedup 1.0000x reference)
#include <cuda_runtime.h>
#include <math.h>

#define THREADS 256
#define ROWS 128
#define LDA 72       // act smem row stride (64+8): 72%32==8 -> conflict-free LDS.64 frags
#define LDP 136      // P/q smem row stride (128+8): 136%32==8

// smem float offsets
#define OFF_P   0        // 128*136 = 17408 (q then P)
#define OFF_ACT 17408    // 2 x 128*72 = 18432 (ends 35840)
#define OFF_W   35840    // 2 x 8192 = 16384 (ends 52224)
#define OFF_WO  17408    // phase C: 2 x 16384 = 32768 (overlays ACT+W, ends 50176)
#define OFF_S   52224    // 512 (s[row][head])
#define OFF_BO  52736    // 512
#define OFF_G   53248    // 512
#define OFF_N2  53760    // 64
#define OFF_RS  53824    // 64
#define SMEM_FLOATS 53888   // 215552 bytes

// frag-major tf32 weights, k-permuted (frag slot j: k = 8*(j>>1) + 2*lm + (j&1))
__device__ float WqF[32 * 2048];    // [h16][T16][lane][4]
__device__ float WkF[48 * 2048];
__device__ float WvF[48 * 2048];
__device__ float WoF[8 * 8192];     // [h16][T64][lane][4]

__device__ __forceinline__ unsigned tf32_bits(float x) {
    unsigned u; asm("cvt.rna.tf32.f32 %0, %1;" : "=r"(u) : "f"(x)); return u;
}
__device__ __forceinline__ float tf32f(float x) { return __uint_as_float(tf32_bits(x)); }

__device__ __forceinline__ void mma8(float* d, unsigned a0, unsigned a1, unsigned a2, unsigned a3,
                                     unsigned b0, unsigned b1) {
    asm volatile(
        "mma.sync.aligned.m16n8k8.row.col.f32.tf32.tf32.f32 "
        "{%0,%1,%2,%3},{%4,%5,%6,%7},{%8,%9},{%0,%1,%2,%3};"
        : "+f"(d[0]), "+f"(d[1]), "+f"(d[2]), "+f"(d[3])
        : "r"(a0), "r"(a1), "r"(a2), "r"(a3), "r"(b0), "r"(b1));
}

#define CP_COMMIT() asm volatile("cp.async.commit_group;")
#define CP_WAIT0()  asm volatile("cp.async.wait_group 0;")

__device__ __forceinline__ void cp16(float* smdst, const float* gsrc) {
    unsigned sa = (unsigned)__cvta_generic_to_shared(smdst);
    asm volatile("cp.async.cg.shared.global [%0], [%1], 16;" :: "r"(sa), "l"(gsrc));
}

// activations: 128 rows x 64 cols -> smem [r*LDA + c]
__device__ __forceinline__ void act_cp(float* sm, int dstOff, const float* A,
                                       size_t rowBase, int gld, int kb, int tid) {
#pragma unroll
    for (int i = 0; i < 8; i++) {
        const int idx = tid + THREADS * i;          // 0..2047
        const int r = idx >> 4, q = (idx & 15) * 4;
        cp16(&sm[dstOff + r * LDA + q], A + (rowBase + r) * (size_t)gld + kb + q);
    }
}

template <int NF>
__device__ __forceinline__ void w_cp(float* sm, int dstOff, const float* gsrc, int tid) {
#pragma unroll
    for (int i = tid * 4; i < NF; i += THREADS * 4)
        cp16(&sm[dstOff + i], gsrc + i);
}

// ---------------- prep: row-major fp32 -> frag-major tf32, k-permuted ----------------
__global__ void __launch_bounds__(256)
lca_prep(const float* __restrict__ Wq, const float* __restrict__ Wk,
         const float* __restrict__ Wv, const float* __restrict__ Wo)
{
    const int idx = blockIdx.x * 256 + threadIdx.x;   // < 327680
    if (idx < 65536) {                                 // WqF: K=512, 128 cols
        int i = idx;
        int j = i & 3, lane = (i >> 2) & 31, T = (i >> 7) & 15, h16 = i >> 11;
        int lm = lane & 3, l4 = lane >> 2;
        int k = h16 * 16 + 8 * (j >> 1) + 2 * lm + (j & 1);
        WqF[i] = tf32f(Wq[k * 128 + T * 8 + l4]);
    } else if (idx < 65536 + 98304) {                  // WkF: K=768
        int i = idx - 65536;
        int j = i & 3, lane = (i >> 2) & 31, T = (i >> 7) & 15, h16 = i >> 11;
        int lm = lane & 3, l4 = lane >> 2;
        int k = h16 * 16 + 8 * (j >> 1) + 2 * lm + (j & 1);
        WkF[i] = tf32f(Wk[k * 128 + T * 8 + l4]);
    } else if (idx < 65536 + 2 * 98304) {              // WvF
        int i = idx - 65536 - 98304;
        int j = i & 3, lane = (i >> 2) & 31, T = (i >> 7) & 15, h16 = i >> 11;
        int lm = lane & 3, l4 = lane >> 2;
        int k = h16 * 16 + 8 * (j >> 1) + 2 * lm + (j & 1);
        WvF[i] = tf32f(Wv[k * 128 + T * 8 + l4]);
    } else {                                           // WoF: K=128, 512 cols
        int i = idx - 65536 - 2 * 98304;
        int j = i & 3, lane = (i >> 2) & 31, T = (i >> 7) & 63, h16 = i >> 13;
        int lm = lane & 3, l4 = lane >> 2;
        int k = h16 * 16 + 8 * (j >> 1) + 2 * lm + (j & 1);
        WoF[i] = tf32f(Wo[k * 512 + T * 8 + l4]);
    }
}

// ---------------------------------- main ----------------------------------
__global__ void __launch_bounds__(THREADS, 1)
lca_tc(const float* __restrict__ x, const float* __restrict__ ctx,
       const float* __restrict__ bo, const float* __restrict__ g,
       float* __restrict__ out)
{
    extern __shared__ float sm[];
    const int tid  = threadIdx.x;
    const int lane = tid & 31;
    const int warp = tid >> 5;           // 0..7
    const int l4   = lane >> 2;
    const int lm   = lane & 3;
    const int band = warp >> 1;          // A/B: 4 bands x 32 rows
    const int cg   = warp & 1;           //      2 colgrps x 64 cols
    const size_t Rbase = (size_t)blockIdx.x * ROWS;

    for (int i = tid; i < 512; i += THREADS) {
        sm[OFF_BO + i] = __ldg(&bo[i]);
        sm[OFF_G + i]  = __ldg(&g[i]);
    }
    if (tid < 64) sm[OFF_N2 + tid] = 0.f;

    const int rA0 = band * 32 + l4;      // row (m=0 half); +16 for m=1; +8 for hi

    // ======================= Phase A: q = x @ Wq (8 chunks of 64k) =======================
    {
        float qa[2][8][4];
#pragma unroll
        for (int m = 0; m < 2; m++)
#pragma unroll
            for (int t = 0; t < 8; t++)
#pragma unroll
                for (int j = 0; j < 4; j++) qa[m][t][j] = 0.f;

        act_cp(sm, OFF_ACT, x, Rbase, 512, 0, tid);
        w_cp<8192>(sm, OFF_W, WqF, tid);
        CP_COMMIT();

#pragma unroll 1
        for (int c = 0; c < 8; c++) {
            const int cb = c & 1;
            CP_WAIT0();
            __syncthreads();
            if (c + 1 < 8) {
                act_cp(sm, OFF_ACT + (cb ^ 1) * 9216, x, Rbase, 512, (c + 1) * 64, tid);
                w_cp<8192>(sm, OFF_W + (cb ^ 1) * 8192, WqF + (c + 1) * 8192, tid);
                CP_COMMIT();
            }
            const float* AB = &sm[OFF_ACT + cb * 9216];
            const float* WB = &sm[OFF_W + cb * 8192];
#pragma unroll
            for (int hf = 0; hf < 4; hf++) {
                unsigned aa[2][2][4];    // [ks2][m]
#pragma unroll
                for (int ks2 = 0; ks2 < 2; ks2++) {
                    const int k = hf * 16 + ks2 * 8 + 2 * lm;
#pragma unroll
                    for (int m = 0; m < 2; m++) {
                        const float2 lo = *(const float2*)&AB[(rA0 + m * 16) * LDA + k];
                        const float2 hi = *(const float2*)&AB[(rA0 + m * 16 + 8) * LDA + k];
                        aa[ks2][m][0] = tf32_bits(lo.x);
                        aa[ks2][m][1] = tf32_bits(hi.x);
                        aa[ks2][m][2] = tf32_bits(lo.y);
                        aa[ks2][m][3] = tf32_bits(hi.y);
                    }
                }
#pragma unroll
                for (int t = 0; t < 8; t++) {
                    const float4 Bt = *(const float4*)&WB[hf * 2048 + (cg * 8 + t) * 128 + lane * 4];
#pragma unroll
                    for (int ks2 = 0; ks2 < 2; ks2++) {
                        const unsigned b0 = __float_as_uint(ks2 ? Bt.z : Bt.x);
                        const unsigned b1 = __float_as_uint(ks2 ? Bt.w : Bt.y);
                        mma8(qa[0][t], aa[ks2][0][0], aa[ks2][0][1], aa[ks2][0][2], aa[ks2][0][3], b0, b1);
                        mma8(qa[1][t], aa[ks2][1][0], aa[ks2][1][1], aa[ks2][1][2], aa[ks2][1][3], b0, b1);
                    }
                }
            }
        }

        // issue B1 chunk0 copies before epilogue (overlap)
        act_cp(sm, OFF_ACT, ctx, Rbase, 768, 0, tid);
        w_cp<8192>(sm, OFF_W, WkF, tid);
        CP_COMMIT();

        // epilogue: write raw q to P region
#pragma unroll
        for (int m = 0; m < 2; m++) {
            const int rA = rA0 + m * 16;
#pragma unroll
            for (int t = 0; t < 8; t++) {
                const int col = (cg * 8 + t) * 8 + 2 * lm;
                *(float2*)&sm[OFF_P + rA * LDP + col]       = make_float2(qa[m][t][0], qa[m][t][1]);
                *(float2*)&sm[OFF_P + (rA + 8) * LDP + col] = make_float2(qa[m][t][2], qa[m][t][3]);
            }
        }
    }
    __syncthreads();

    // softmax per (row, head), *scale, in place
#pragma unroll 1
    for (int task = tid; task < ROWS * 4; task += THREADS) {
        const int r = task >> 2, h = task & 3;
        float* qp = &sm[OFF_P + r * LDP + h * 32];
        float mx = qp[0];
#pragma unroll
        for (int i = 1; i < 32; i++) mx = fmaxf(mx, qp[i]);
        float s = 0.f;
#pragma unroll
        for (int i = 0; i < 32; i++) s += __expf(qp[i] - mx);
        const float inv = 0.17677669529663687f / s;   // 32^-0.5 / sum
#pragma unroll
        for (int i = 0; i < 32; i++) qp[i] = __expf(qp[i] - mx) * inv;
    }

    // ===== Phase B1: k = sigmoid(ctx@Wk); s = q.k (12 chunks of 64k) =====
    {
        float ka[2][8][4];
#pragma unroll
        for (int m = 0; m < 2; m++)
#pragma unroll
            for (int t = 0; t < 8; t++)
#pragma unroll
                for (int j = 0; j < 4; j++) ka[m][t][j] = 0.f;

#pragma unroll 1
        for (int c = 0; c < 12; c++) {
            const int cb = c & 1;
            CP_WAIT0();
            __syncthreads();
            if (c + 1 < 12) {
                act_cp(sm, OFF_ACT + (cb ^ 1) * 9216, ctx, Rbase, 768, (c + 1) * 64, tid);
                w_cp<8192>(sm, OFF_W + (cb ^ 1) * 8192, WkF + (c + 1) * 8192, tid);
                CP_COMMIT();
            }
            const float* AB = &sm[OFF_ACT + cb * 9216];
            const float* WB = &sm[OFF_W + cb * 8192];
#pragma unroll
            for (int hf = 0; hf < 4; hf++) {
                unsigned aa[2][2][4];
#pragma unroll
                for (int ks2 = 0; ks2 < 2; ks2++) {
                    const int k = hf * 16 + ks2 * 8 + 2 * lm;
#pragma unroll
                    for (int m = 0; m < 2; m++) {
                        const float2 lo = *(const float2*)&AB[(rA0 + m * 16) * LDA + k];
                        const float2 hi = *(const float2*)&AB[(rA0 + m * 16 + 8) * LDA + k];
                        aa[ks2][m][0] = tf32_bits(lo.x);
                        aa[ks2][m][1] = tf32_bits(hi.x);
                        aa[ks2][m][2] = tf32_bits(lo.y);
                        aa[ks2][m][3] = tf32_bits(hi.y);
                    }
                }
#pragma unroll
                for (int t = 0; t < 8; t++) {
                    const float4 Bt = *(const float4*)&WB[hf * 2048 + (cg * 8 + t) * 128 + lane * 4];
#pragma unroll
                    for (int ks2 = 0; ks2 < 2; ks2++) {
                        const unsigned b0 = __float_as_uint(ks2 ? Bt.z : Bt.x);
                        const unsigned b1 = __float_as_uint(ks2 ? Bt.w : Bt.y);
                        mma8(ka[0][t], aa[ks2][0][0], aa[ks2][0][1], aa[ks2][0][2], aa[ks2][0][3], b0, b1);
                        mma8(ka[1][t], aa[ks2][1][0], aa[ks2][1][1], aa[ks2][1][2], aa[ks2][1][3], b0, b1);
                    }
                }
            }
        }

        // issue B2 chunk0 copies before epilogue
        act_cp(sm, OFF_ACT, ctx, Rbase, 768, 0, tid);
        w_cp<8192>(sm, OFF_W, WvF, tid);
        CP_COMMIT();

        // epilogue: s[row][head] = q . sigmoid(k)  (head = cg*2 + (t>>2))
#pragma unroll
        for (int m = 0; m < 2; m++) {
            const int rA = rA0 + m * 16;
            float d0[2] = {0.f, 0.f}, d1[2] = {0.f, 0.f};
#pragma unroll
            for (int t = 0; t < 8; t++) {
                const int hh = t >> 2;
                const int col = (cg * 8 + t) * 8 + 2 * lm;
                const float2 q1 = *(const float2*)&sm[OFF_P + rA * LDP + col];
                const float2 q2 = *(const float2*)&sm[OFF_P + (rA + 8) * LDP + col];
                d0[hh] += q1.x / (1.f + __expf(-ka[m][t][0])) + q1.y / (1.f + __expf(-ka[m][t][1]));
                d1[hh] += q2.x / (1.f + __expf(-ka[m][t][2])) + q2.y / (1.f + __expf(-ka[m][t][3]));
            }
#pragma unroll
            for (int hh = 0; hh < 2; hh++) {
                d0[hh] += __shfl_xor_sync(0xffffffffu, d0[hh], 1);
                d0[hh] += __shfl_xor_sync(0xffffffffu, d0[hh], 2);
                d1[hh] += __shfl_xor_sync(0xffffffffu, d1[hh], 1);
                d1[hh] += __shfl_xor_sync(0xffffffffu, d1[hh], 2);
                if (lm == 0) {
                    sm[OFF_S + rA * 4 + cg * 2 + hh]       = d0[hh];
                    sm[OFF_S + (rA + 8) * 4 + cg * 2 + hh] = d1[hh];
                }
            }
        }
    }

    // ===== Phase B2: v = ctx@Wv; P = s*v (12 chunks of 64k) =====
    {
        float va[2][8][4];
#pragma unroll
        for (int m = 0; m < 2; m++)
#pragma unroll
            for (int t = 0; t < 8; t++)
#pragma unroll
                for (int j = 0; j < 4; j++) va[m][t][j] = 0.f;

#pragma unroll 1
        for (int c = 0; c < 12; c++) {
            const int cb = c & 1;
            CP_WAIT0();
            __syncthreads();
            if (c + 1 < 12) {
                act_cp(sm, OFF_ACT + (cb ^ 1) * 9216, ctx, Rbase, 768, (c + 1) * 64, tid);
                w_cp<8192>(sm, OFF_W + (cb ^ 1) * 8192, WvF + (c + 1) * 8192, tid);
                CP_COMMIT();
            }
            const float* AB = &sm[OFF_ACT + cb * 9216];
            const float* WB = &sm[OFF_W + cb * 8192];
#pragma unroll
            for (int hf = 0; hf < 4; hf++) {
                unsigned aa[2][2][4];
#pragma unroll
                for (int ks2 = 0; ks2 < 2; ks2++) {
                    const int k = hf * 16 + ks2 * 8 + 2 * lm;
#pragma unroll
                    for (int m = 0; m < 2; m++) {
                        const float2 lo = *(const float2*)&AB[(rA0 + m * 16) * LDA + k];
                        const float2 hi = *(const float2*)&AB[(rA0 + m * 16 + 8) * LDA + k];
                        aa[ks2][m][0] = tf32_bits(lo.x);
                        aa[ks2][m][1] = tf32_bits(hi.x);
                        aa[ks2][m][2] = tf32_bits(lo.y);
                        aa[ks2][m][3] = tf32_bits(hi.y);
                    }
                }
#pragma unroll
                for (int t = 0; t < 8; t++) {
                    const float4 Bt = *(const float4*)&WB[hf * 2048 + (cg * 8 + t) * 128 + lane * 4];
#pragma unroll
                    for (int ks2 = 0; ks2 < 2; ks2++) {
                        const unsigned b0 = __float_as_uint(ks2 ? Bt.z : Bt.x);
                        const unsigned b1 = __float_as_uint(ks2 ? Bt.w : Bt.y);
                        mma8(va[0][t], aa[ks2][0][0], aa[ks2][0][1], aa[ks2][0][2], aa[ks2][0][3], b0, b1);
                        mma8(va[1][t], aa[ks2][1][0], aa[ks2][1][1], aa[ks2][1][2], aa[ks2][1][3], b0, b1);
                    }
                }
            }
        }

        // all act/W reads done; OFF_WO overlays them -> sync before Wo copy
        __syncthreads();
        w_cp<16384>(sm, OFF_WO, WoF, tid);
        CP_COMMIT();

        // epilogue: P = s * v (stored tf32, consumed as permuted A-frags)
#pragma unroll
        for (int m = 0; m < 2; m++) {
            const int rA = rA0 + m * 16;
#pragma unroll
            for (int t = 0; t < 8; t++) {
                const int hh = t >> 2;
                const float s0 = sm[OFF_S + rA * 4 + cg * 2 + hh];
                const float s1 = sm[OFF_S + (rA + 8) * 4 + cg * 2 + hh];
                const int col = (cg * 8 + t) * 8 + 2 * lm;
                *(float2*)&sm[OFF_P + rA * LDP + col] =
                    make_float2(tf32f(s0 * va[m][t][0]), tf32f(s0 * va[m][t][1]));
                *(float2*)&sm[OFF_P + (rA + 8) * LDP + col] =
                    make_float2(tf32f(s1 * va[m][t][2]), tf32f(s1 * va[m][t][3]));
            }
        }
    }

    // ===== Phase C: y = P @ Wo + bo, fused RMSNorm; 2 subpasses of 64 rows =====
    const int band2 = warp >> 2;   // 2 bands x 32 rows
    const int cg2   = warp & 3;    // 4 colgrps x 128 cols
#pragma unroll 1
    for (int sp = 0; sp < 2; sp++) {
        float facc[2][16][4];
#pragma unroll
        for (int m = 0; m < 2; m++)
#pragma unroll
            for (int t = 0; t < 16; t++)
#pragma unroll
                for (int j = 0; j < 4; j++) facc[m][t][j] = 0.f;

#pragma unroll 1
        for (int c = 0; c < 4; c++) {
            const int cb = c & 1;
            CP_WAIT0();
            __syncthreads();
            if (!(sp == 1 && c == 3)) {
                const int nc = (c + 1) & 3;
                w_cp<16384>(sm, OFF_WO + (cb ^ 1) * 16384, WoF + nc * 16384, tid);
                CP_COMMIT();
            }
            const float* WOB = &sm[OFF_WO + cb * 16384];
#pragma unroll
            for (int hf = 0; hf < 2; hf++) {
                unsigned aa[2][2][4];
#pragma unroll
                for (int ks2 = 0; ks2 < 2; ks2++) {
                    const int k = c * 32 + hf * 16 + ks2 * 8 + 2 * lm;
#pragma unroll
                    for (int m = 0; m < 2; m++) {
                        const int rr = sp * 64 + band2 * 32 + m * 16 + l4;
                        const float2 lo = *(const float2*)&sm[OFF_P + rr * LDP + k];
                        const float2 hi = *(const float2*)&sm[OFF_P + (rr + 8) * LDP + k];
                        aa[ks2][m][0] = __float_as_uint(lo.x);
                        aa[ks2][m][1] = __float_as_uint(hi.x);
                        aa[ks2][m][2] = __float_as_uint(lo.y);
                        aa[ks2][m][3] = __float_as_uint(hi.y);
                    }
                }
#pragma unroll
                for (int t = 0; t < 16; t++) {
                    const float4 Bt = *(const float4*)&WOB[hf * 8192 + (cg2 * 16 + t) * 128 + lane * 4];
#pragma unroll
                    for (int ks2 = 0; ks2 < 2; ks2++) {
                        const unsigned b0 = __float_as_uint(ks2 ? Bt.z : Bt.x);
                        const unsigned b1 = __float_as_uint(ks2 ? Bt.w : Bt.y);
                        mma8(facc[0][t], aa[ks2][0][0], aa[ks2][0][1], aa[ks2][0][2], aa[ks2][0][3], b0, b1);
                        mma8(facc[1][t], aa[ks2][1][0], aa[ks2][1][1], aa[ks2][1][2], aa[ks2][1][3], b0, b1);
                    }
                }
            }
        }

        // epilogue: +bo, row sumsq, norm, scale, store
        float ssA[2] = {0.f, 0.f}, ssB[2] = {0.f, 0.f};
#pragma unroll
        for (int m = 0; m < 2; m++)
#pragma unroll
            for (int t = 0; t < 16; t++) {
                const int col = cg2 * 128 + t * 8 + 2 * lm;
                const float2 b2 = *(const float2*)&sm[OFF_BO + col];
                facc[m][t][0] += b2.x; facc[m][t][1] += b2.y;
                facc[m][t][2] += b2.x; facc[m][t][3] += b2.y;
                ssA[m] += facc[m][t][0] * facc[m][t][0] + facc[m][t][1] * facc[m][t][1];
                ssB[m] += facc[m][t][2] * facc[m][t][2] + facc[m][t][3] * facc[m][t][3];
            }
#pragma unroll
        for (int m = 0; m < 2; m++) {
            ssA[m] += __shfl_xor_sync(0xffffffffu, ssA[m], 1);
            ssA[m] += __shfl_xor_sync(0xffffffffu, ssA[m], 2);
            ssB[m] += __shfl_xor_sync(0xffffffffu, ssB[m], 1);
            ssB[m] += __shfl_xor_sync(0xffffffffu, ssB[m], 2);
            if (lm == 0) {
                atomicAdd(&sm[OFF_N2 + band2 * 32 + m * 16 + l4], ssA[m]);
                atomicAdd(&sm[OFF_N2 + band2 * 32 + m * 16 + l4 + 8], ssB[m]);
            }
        }
        __syncthreads();
        if (tid < 64) {
            sm[OFF_RS + tid] = 22.627416997969522f / fmaxf(sqrtf(sm[OFF_N2 + tid]), 1e-12f);
            sm[OFF_N2 + tid] = 0.f;
        }
        __syncthreads();

#pragma unroll
        for (int m = 0; m < 2; m++) {
            const int rloc = band2 * 32 + m * 16 + l4;
            const float cA = sm[OFF_RS + rloc], cB = sm[OFF_RS + rloc + 8];
            const size_t gr = (Rbase + sp * 64 + rloc) * 512;
#pragma unroll
            for (int t = 0; t < 16; t++) {
                const int col = cg2 * 128 + t * 8 + 2 * lm;
                const float2 g2 = *(const float2*)&sm[OFF_G + col];
                *(float2*)&out[gr + col] =
                    make_float2(facc[m][t][0] * cA * g2.x, facc[m][t][1] * cA * g2.y);
                *(float2*)&out[gr + 8 * 512 + col] =
                    make_float2(facc[m][t][2] * cB * g2.x, facc[m][t][3] * cB * g2.y);
            }
        }
    }
}

extern "C" void kernel_launch(void* const* d_in, const int* in_sizes, int n_in,
                              void* d_out, int out_size)
{
    const float* x   = (const float*)d_in[0];
    const float* ctx = (const float*)d_in[1];
    const float* Wq  = (const float*)d_in[2];
    const float* Wk  = (const float*)d_in[3];
    const float* Wv  = (const float*)d_in[4];
    const float* Wo  = (const float*)d_in[5];
    const float* bo  = (const float*)d_in[6];
    const float* g   = (const float*)d_in[7];
    float* out = (float*)d_out;

    const int B = in_sizes[0] / 512;   // 65536
    const size_t SMEM = (size_t)SMEM_FLOATS * sizeof(float);

    lca_prep<<<1280, 256>>>(Wq, Wk, Wv, Wo);

    cudaFuncSetAttribute(lca_tc, cudaFuncAttributeMaxDynamicSharedMemorySize, (int)SMEM);
    lca_tc<<<B / ROWS, THREADS, SMEM>>>(x, ctx, bo, g, out);
}

// round 7
// speedup vs baseline: 1.0794x; 1.0794x over previous
#include <cuda_runtime.h>
#include <math.h>

#define THREADS 256
#define ROWS 64
#define LDA 36    // phase A act stride (32+4), conflict-free frag LDS
#define LDB 20    // phase B act stride (16+4), conflict-free frag LDS
#define LDP 132   // P stride (128+4)

// smem float offsets (total 25984 floats = 103936 B; 2 CTAs/SM = 207.9KB <= 228KB)
#define OFF_P   0        // 64*132 = 8448
#define OFF_ACT 8448     // A: 2*2304=4608 ; B: 2*1280=2560
#define OFF_W   13056    // A: 2*4096 ; B: 2*(2048+2048) -> 8192 (ends 21248)
#define OFF_WO  8448     // C: 2*8192 = 16384 (overlays ACT+W, ends 24832)
#define OFF_BO  24832    // 512
#define OFF_G   25344    // 512
#define OFF_N2  25856    // 64
#define OFF_RS  25920    // 64
#define SMEM_FLOATS 25984

// frag-major tf32 weights (R4-verified layout):
// proj: [kchunk16][T16][lane][j]  with k = h16*16 + lm + 4j, col = T*8 + l4
__device__ float WqF[32 * 2048];
__device__ float WkF[48 * 2048];
__device__ float WvF[48 * 2048];
__device__ float WoF[8 * 8192];    // [kchunk16][T64][lane][j], col = T*8+l4 (512 cols)

__device__ __forceinline__ unsigned tf32_bits(float x) {
    unsigned u; asm("cvt.rna.tf32.f32 %0, %1;" : "=r"(u) : "f"(x)); return u;
}
__device__ __forceinline__ float tf32f(float x) { return __uint_as_float(tf32_bits(x)); }

__device__ __forceinline__ void mma8(float* d, unsigned a0, unsigned a1, unsigned a2, unsigned a3,
                                     unsigned b0, unsigned b1) {
    asm volatile(
        "mma.sync.aligned.m16n8k8.row.col.f32.tf32.tf32.f32 "
        "{%0,%1,%2,%3},{%4,%5,%6,%7},{%8,%9},{%0,%1,%2,%3};"
        : "+f"(d[0]), "+f"(d[1]), "+f"(d[2]), "+f"(d[3])
        : "r"(a0), "r"(a1), "r"(a2), "r"(a3), "r"(b0), "r"(b1));
}

#define CP_COMMIT() asm volatile("cp.async.commit_group;")
#define CP_WAIT0()  asm volatile("cp.async.wait_group 0;")

__device__ __forceinline__ void cp16(float* smdst, const float* gsrc) {
    unsigned sa = (unsigned)__cvta_generic_to_shared(smdst);
    asm volatile("cp.async.cg.shared.global [%0], [%1], 16;" :: "r"(sa), "l"(gsrc));
}

// 64 rows x 32 cols -> [r*LDA + c]
__device__ __forceinline__ void act_cp32(float* sm, int dstOff, const float* A,
                                         size_t rowBase, int gld, int kb, int tid) {
#pragma unroll
    for (int i = 0; i < 2; i++) {
        const int idx = tid + THREADS * i;       // 0..511
        const int r = idx >> 3, q = (idx & 7) * 4;
        cp16(&sm[dstOff + r * LDA + q], A + (rowBase + r) * (size_t)gld + kb + q);
    }
}
// 64 rows x 16 cols -> [r*LDB + c]
__device__ __forceinline__ void act_cp16(float* sm, int dstOff, const float* A,
                                         size_t rowBase, int gld, int kb, int tid) {
    const int r = tid >> 2, q = (tid & 3) * 4;
    cp16(&sm[dstOff + r * LDB + q], A + (rowBase + r) * (size_t)gld + kb + q);
}

template <int NF>
__device__ __forceinline__ void w_cp(float* sm, int dstOff, const float* gsrc, int tid) {
#pragma unroll
    for (int i = tid * 4; i < NF; i += THREADS * 4)
        cp16(&sm[dstOff + i], gsrc + i);
}

// ---------------- prep: fp32 row-major -> frag-major tf32 (R4 layout) ----------------
__global__ void __launch_bounds__(256)
lca_prep(const float* __restrict__ Wq, const float* __restrict__ Wk,
         const float* __restrict__ Wv, const float* __restrict__ Wo)
{
    const int idx = blockIdx.x * 256 + threadIdx.x;   // < 327680
    if (idx < 65536) {                                 // WqF
        int i = idx;
        int j = i & 3, lane = (i >> 2) & 31, T = (i >> 7) & 15, h16 = i >> 11;
        int lm = lane & 3, l4 = lane >> 2;
        int k = h16 * 16 + lm + 4 * j;
        WqF[i] = tf32f(Wq[k * 128 + T * 8 + l4]);
    } else if (idx < 65536 + 98304) {                  // WkF
        int i = idx - 65536;
        int j = i & 3, lane = (i >> 2) & 31, T = (i >> 7) & 15, h16 = i >> 11;
        int lm = lane & 3, l4 = lane >> 2;
        int k = h16 * 16 + lm + 4 * j;
        WkF[i] = tf32f(Wk[k * 128 + T * 8 + l4]);
    } else if (idx < 65536 + 2 * 98304) {              // WvF
        int i = idx - 65536 - 98304;
        int j = i & 3, lane = (i >> 2) & 31, T = (i >> 7) & 15, h16 = i >> 11;
        int lm = lane & 3, l4 = lane >> 2;
        int k = h16 * 16 + lm + 4 * j;
        WvF[i] = tf32f(Wv[k * 128 + T * 8 + l4]);
    } else {                                           // WoF
        int i = idx - 65536 - 2 * 98304;
        int j = i & 3, lane = (i >> 2) & 31, T = (i >> 7) & 63, h16 = i >> 13;
        int lm = lane & 3, l4 = lane >> 2;
        int k = h16 * 16 + lm + 4 * j;
        WoF[i] = tf32f(Wo[k * 512 + T * 8 + l4]);
    }
}

// ---------------------------------- main ----------------------------------
__global__ void __launch_bounds__(THREADS, 2)
lca_tc(const float* __restrict__ x, const float* __restrict__ ctx,
       const float* __restrict__ bo, const float* __restrict__ g,
       float* __restrict__ out)
{
    extern __shared__ float sm[];
    const int tid  = threadIdx.x;
    const int lane = tid & 31;
    const int warp = tid >> 5;           // 0..7
    const int l4   = lane >> 2;
    const int lm   = lane & 3;
    const int band = warp >> 1;          // A/B: 4 bands x 16 rows
    const int cg   = warp & 1;           //      2 colgrps x 64 cols (2 heads each)
    const size_t Rbase = (size_t)blockIdx.x * ROWS;

    for (int i = tid; i < 512; i += THREADS) {
        sm[OFF_BO + i] = __ldg(&bo[i]);
        sm[OFF_G + i]  = __ldg(&g[i]);
    }
    if (tid < 64) sm[OFF_N2 + tid] = 0.f;

    const int rA0 = band * 16 + l4;      // lane's rows: rA0 and rA0+8

    // ============== Phase A: q = x @ Wq (16 chunks of 32k) ==============
    {
        float qa[8][4];
#pragma unroll
        for (int t = 0; t < 8; t++)
#pragma unroll
            for (int j = 0; j < 4; j++) qa[t][j] = 0.f;

        act_cp32(sm, OFF_ACT, x, Rbase, 512, 0, tid);
        w_cp<4096>(sm, OFF_W, WqF, tid);
        CP_COMMIT();

#pragma unroll 1
        for (int c = 0; c < 16; c++) {
            const int cb = c & 1;
            CP_WAIT0();
            __syncthreads();
            if (c + 1 < 16) {
                act_cp32(sm, OFF_ACT + (cb ^ 1) * 2304, x, Rbase, 512, (c + 1) * 32, tid);
                w_cp<4096>(sm, OFF_W + (cb ^ 1) * 4096, WqF + (c + 1) * 4096, tid);
                CP_COMMIT();
            }
            const float* AB = &sm[OFF_ACT + cb * 2304];
            const float* WB = &sm[OFF_W + cb * 4096];
#pragma unroll
            for (int hf = 0; hf < 2; hf++) {
                unsigned aa[2][4];
#pragma unroll
                for (int ks2 = 0; ks2 < 2; ks2++) {
                    const float* Ap = &AB[rA0 * LDA + hf * 16 + ks2 * 8 + lm];
                    aa[ks2][0] = tf32_bits(Ap[0]);
                    aa[ks2][1] = tf32_bits(Ap[8 * LDA]);
                    aa[ks2][2] = tf32_bits(Ap[4]);
                    aa[ks2][3] = tf32_bits(Ap[8 * LDA + 4]);
                }
#pragma unroll
                for (int t = 0; t < 8; t++) {
                    const float4 Bt = *(const float4*)&WB[hf * 2048 + (cg * 8 + t) * 128 + lane * 4];
#pragma unroll
                    for (int ks2 = 0; ks2 < 2; ks2++) {
                        const unsigned b0 = __float_as_uint(ks2 ? Bt.z : Bt.x);
                        const unsigned b1 = __float_as_uint(ks2 ? Bt.w : Bt.y);
                        mma8(qa[t], aa[ks2][0], aa[ks2][1], aa[ks2][2], aa[ks2][3], b0, b1);
                    }
                }
            }
        }

        // issue phase-B chunk0 copies (disjoint buffers from A's last-read buf1)
        act_cp16(sm, OFF_ACT, ctx, Rbase, 768, 0, tid);
        w_cp<2048>(sm, OFF_W, WkF, tid);
        w_cp<2048>(sm, OFF_W + 2048, WvF, tid);
        CP_COMMIT();

        // store raw q to P
#pragma unroll
        for (int t = 0; t < 8; t++) {
            const int col = (cg * 8 + t) * 8 + 2 * lm;
            *(float2*)&sm[OFF_P + rA0 * LDP + col]       = make_float2(qa[t][0], qa[t][1]);
            *(float2*)&sm[OFF_P + (rA0 + 8) * LDP + col] = make_float2(qa[t][2], qa[t][3]);
        }
    }
    __syncthreads();

    // softmax per (row, head), *scale, in place: 256 tasks, 1/thread
    {
        const int r = tid >> 2, h = tid & 3;
        float* qp = &sm[OFF_P + r * LDP + h * 32];
        float mx = qp[0];
#pragma unroll
        for (int i = 1; i < 32; i++) mx = fmaxf(mx, qp[i]);
        float s = 0.f;
#pragma unroll
        for (int i = 0; i < 32; i++) s += __expf(qp[i] - mx);
        const float inv = 0.17677669529663687f / s;   // 32^-0.5 / sum
#pragma unroll
        for (int i = 0; i < 32; i++) qp[i] = __expf(qp[i] - mx) * inv;
    }

    // ===== Phase B: k=sigmoid(ctx@Wk), v=ctx@Wv, s=q.k, P=s*v (48 chunks of 16k) =====
    {
        float ka[8][4], va[8][4];
#pragma unroll
        for (int t = 0; t < 8; t++)
#pragma unroll
            for (int j = 0; j < 4; j++) { ka[t][j] = 0.f; va[t][j] = 0.f; }

#pragma unroll 1
        for (int c = 0; c < 48; c++) {
            const int cb = c & 1;
            CP_WAIT0();
            __syncthreads();
            if (c + 1 < 48) {
                act_cp16(sm, OFF_ACT + (cb ^ 1) * 1280, ctx, Rbase, 768, (c + 1) * 16, tid);
                w_cp<2048>(sm, OFF_W + (cb ^ 1) * 4096, WkF + (c + 1) * 2048, tid);
                w_cp<2048>(sm, OFF_W + (cb ^ 1) * 4096 + 2048, WvF + (c + 1) * 2048, tid);
                CP_COMMIT();
            }
            const float* AB = &sm[OFF_ACT + cb * 1280];
            const float* KB = &sm[OFF_W + cb * 4096];
            const float* VB = KB + 2048;

            unsigned aa[2][4];
#pragma unroll
            for (int ks2 = 0; ks2 < 2; ks2++) {
                const float* Ap = &AB[rA0 * LDB + ks2 * 8 + lm];
                aa[ks2][0] = tf32_bits(Ap[0]);
                aa[ks2][1] = tf32_bits(Ap[8 * LDB]);
                aa[ks2][2] = tf32_bits(Ap[4]);
                aa[ks2][3] = tf32_bits(Ap[8 * LDB + 4]);
            }
#pragma unroll
            for (int t = 0; t < 8; t++) {
                const int toff = (cg * 8 + t) * 128 + lane * 4;
                const float4 BtK = *(const float4*)&KB[toff];
                const float4 BtV = *(const float4*)&VB[toff];
#pragma unroll
                for (int ks2 = 0; ks2 < 2; ks2++) {
                    unsigned b0 = __float_as_uint(ks2 ? BtK.z : BtK.x);
                    unsigned b1 = __float_as_uint(ks2 ? BtK.w : BtK.y);
                    mma8(ka[t], aa[ks2][0], aa[ks2][1], aa[ks2][2], aa[ks2][3], b0, b1);
                    b0 = __float_as_uint(ks2 ? BtV.z : BtV.x);
                    b1 = __float_as_uint(ks2 ? BtV.w : BtV.y);
                    mma8(va[t], aa[ks2][0], aa[ks2][1], aa[ks2][2], aa[ks2][3], b0, b1);
                }
            }
        }

        // all ACT/W reads done -> overlay region free for Wo chunk0
        __syncthreads();
        w_cp<8192>(sm, OFF_WO, WoF, tid);
        CP_COMMIT();

        // epilogue: s = q . sigmoid(k) per (row, head = cg*2 + (t>>2)); P = s*v (tf32)
        float d0[2] = {0.f, 0.f}, d1[2] = {0.f, 0.f};
#pragma unroll
        for (int t = 0; t < 8; t++) {
            const int hh = t >> 2;
            const int col = (cg * 8 + t) * 8 + 2 * lm;
            const float2 q1 = *(const float2*)&sm[OFF_P + rA0 * LDP + col];
            const float2 q2 = *(const float2*)&sm[OFF_P + (rA0 + 8) * LDP + col];
            d0[hh] += q1.x / (1.f + __expf(-ka[t][0])) + q1.y / (1.f + __expf(-ka[t][1]));
            d1[hh] += q2.x / (1.f + __expf(-ka[t][2])) + q2.y / (1.f + __expf(-ka[t][3]));
        }
#pragma unroll
        for (int hh = 0; hh < 2; hh++) {
            d0[hh] += __shfl_xor_sync(0xffffffffu, d0[hh], 1);
            d0[hh] += __shfl_xor_sync(0xffffffffu, d0[hh], 2);
            d1[hh] += __shfl_xor_sync(0xffffffffu, d1[hh], 1);
            d1[hh] += __shfl_xor_sync(0xffffffffu, d1[hh], 2);
        }
#pragma unroll
        for (int t = 0; t < 8; t++) {
            const int hh = t >> 2;
            const int col = (cg * 8 + t) * 8 + 2 * lm;
            *(float2*)&sm[OFF_P + rA0 * LDP + col] =
                make_float2(tf32f(d0[hh] * va[t][0]), tf32f(d0[hh] * va[t][1]));
            *(float2*)&sm[OFF_P + (rA0 + 8) * LDP + col] =
                make_float2(tf32f(d1[hh] * va[t][2]), tf32f(d1[hh] * va[t][3]));
        }
    }

    // ===== Phase C: y = P @ Wo + bo, fused RMSNorm; 2 subpasses of 32 rows =====
    const int band2 = warp >> 2;   // 2 bands x 16 rows
    const int cg2   = warp & 3;    // 4 colgrps x 128 cols
#pragma unroll 1
    for (int sp = 0; sp < 2; sp++) {
        float facc[16][4];
#pragma unroll
        for (int t = 0; t < 16; t++)
#pragma unroll
            for (int j = 0; j < 4; j++) facc[t][j] = 0.f;

#pragma unroll 1
        for (int c = 0; c < 8; c++) {
            const int cb = c & 1;
            CP_WAIT0();
            __syncthreads();
            if (!(sp == 1 && c == 7)) {
                const int nc = (c + 1) & 7;
                w_cp<8192>(sm, OFF_WO + (cb ^ 1) * 8192, WoF + nc * 8192, tid);
                CP_COMMIT();
            }
            const float* WOB = &sm[OFF_WO + cb * 8192];

            unsigned aa[2][4];
            const int rr = sp * 32 + band2 * 16 + l4;
#pragma unroll
            for (int ks2 = 0; ks2 < 2; ks2++) {
                const float* Pp = &sm[OFF_P + rr * LDP + c * 16 + ks2 * 8 + lm];
                aa[ks2][0] = __float_as_uint(Pp[0]);
                aa[ks2][1] = __float_as_uint(Pp[8 * LDP]);
                aa[ks2][2] = __float_as_uint(Pp[4]);
                aa[ks2][3] = __float_as_uint(Pp[8 * LDP + 4]);
            }
#pragma unroll
            for (int t = 0; t < 16; t++) {
                const float4 Bt = *(const float4*)&WOB[(cg2 * 16 + t) * 128 + lane * 4];
#pragma unroll
                for (int ks2 = 0; ks2 < 2; ks2++) {
                    const unsigned b0 = __float_as_uint(ks2 ? Bt.z : Bt.x);
                    const unsigned b1 = __float_as_uint(ks2 ? Bt.w : Bt.y);
                    mma8(facc[t], aa[ks2][0], aa[ks2][1], aa[ks2][2], aa[ks2][3], b0, b1);
                }
            }
        }

        // epilogue: +bo, row sumsq, norm, scale, store
        float ssA = 0.f, ssB = 0.f;
#pragma unroll
        for (int t = 0; t < 16; t++) {
            const int col = cg2 * 128 + t * 8 + 2 * lm;
            const float2 b2 = *(const float2*)&sm[OFF_BO + col];
            facc[t][0] += b2.x; facc[t][1] += b2.y;
            facc[t][2] += b2.x; facc[t][3] += b2.y;
            ssA += facc[t][0] * facc[t][0] + facc[t][1] * facc[t][1];
            ssB += facc[t][2] * facc[t][2] + facc[t][3] * facc[t][3];
        }
        ssA += __shfl_xor_sync(0xffffffffu, ssA, 1);
        ssA += __shfl_xor_sync(0xffffffffu, ssA, 2);
        ssB += __shfl_xor_sync(0xffffffffu, ssB, 1);
        ssB += __shfl_xor_sync(0xffffffffu, ssB, 2);
        const int rloc = band2 * 16 + l4;
        if (lm == 0) {
            atomicAdd(&sm[OFF_N2 + rloc], ssA);
            atomicAdd(&sm[OFF_N2 + rloc + 8], ssB);
        }
        __syncthreads();
        if (tid < 32) {
            sm[OFF_RS + tid] = 22.627416997969522f / fmaxf(sqrtf(sm[OFF_N2 + tid]), 1e-12f);
            sm[OFF_N2 + tid] = 0.f;   // ready for next subpass
        }
        __syncthreads();

        {
            const float cA = sm[OFF_RS + rloc], cB = sm[OFF_RS + rloc + 8];
            const size_t gr = (Rbase + sp * 32 + rloc) * 512;
#pragma unroll
            for (int t = 0; t < 16; t++) {
                const int col = cg2 * 128 + t * 8 + 2 * lm;
                const float2 g2 = *(const float2*)&sm[OFF_G + col];
                *(float2*)&out[gr + col] =
                    make_float2(facc[t][0] * cA * g2.x, facc[t][1] * cA * g2.y);
                *(float2*)&out[gr + 8 * 512 + col] =
                    make_float2(facc[t][2] * cB * g2.x, facc[t][3] * cB * g2.y);
            }
        }
    }
}

extern "C" void kernel_launch(void* const* d_in, const int* in_sizes, int n_in,
                              void* d_out, int out_size)
{
    const float* x   = (const float*)d_in[0];
    const float* ctx = (const float*)d_in[1];
    const float* Wq  = (const float*)d_in[2];
    const float* Wk  = (const float*)d_in[3];
    const float* Wv  = (const float*)d_in[4];
    const float* Wo  = (const float*)d_in[5];
    const float* bo  = (const float*)d_in[6];
    const float* g   = (const float*)d_in[7];
    float* out = (float*)d_out;

    const int B = in_sizes[0] / 512;   // 65536
    const size_t SMEM = (size_t)SMEM_FLOATS * sizeof(float);   // 103936 B

    lca_prep<<<1280, 256>>>(Wq, Wk, Wv, Wo);

    cudaFuncSetAttribute(lca_tc, cudaFuncAttributeMaxDynamicSharedMemorySize, (int)SMEM);
    lca_tc<<<B / ROWS, THREADS, SMEM>>>(x, ctx, bo, g, out);
}

// round 11
// speedup vs baseline: 1.5578x; 1.4432x over previous
#include <cuda_runtime.h>
#include <cuda_fp16.h>
#include <math.h>
#include <stdint.h>

#define THREADS 256
#define ROWS 128
#define LDA 40     // act smem row stride (32+8): conflict-free LDS.64 A-frags
#define LDQ 132    // q fp32 stride
#define LDPH 136   // P half stride (conflict-free LDS.32 half2 frags)

// smem float offsets
#define OFF_Q   0        // q fp32 128*132 = 16896 ; phase C: Wo 2 x 8192 overlays
#define OFF_WO  0
#define OFF_PH  16896    // P half: 128*136 halves = 8704 floats
#define OFF_ACT 25600    // 2 x 128*40 = 10240
#define OFF_W   35840    // 2 x 4096 (A: 2048 used; B: k@+0, v@+2048)
#define OFF_BG  44032    // bo 512 | g 512
#define OFF_N2  45056    // 64
#define OFF_RS  45120    // 64
#define SMEM_FLOATS 45184   // 180736 bytes

// frag-major fp16 weights: proj [kc][T16][lane][8h], Wo [c][T64][lane][8h]
// halves: 0,1 = (k=2lm+{0,1}) b0 grp0 ; 2,3 = k+8 b1 grp0 ; 4,5 = k+16 b0 grp1 ; 6,7 = k+24 b1 grp1
__device__ __half WqH[16 * 4096];
__device__ __half WkH[24 * 4096];
__device__ __half WvH[24 * 4096];
__device__ __half WoH[4 * 16384];

__device__ __forceinline__ void mma16(float* d, unsigned a0, unsigned a1, unsigned a2,
                                      unsigned a3, unsigned b0, unsigned b1) {
    asm volatile(
        "mma.sync.aligned.m16n8k16.row.col.f32.f16.f16.f32 "
        "{%0,%1,%2,%3},{%4,%5,%6,%7},{%8,%9},{%0,%1,%2,%3};"
        : "+f"(d[0]), "+f"(d[1]), "+f"(d[2]), "+f"(d[3])
        : "r"(a0), "r"(a1), "r"(a2), "r"(a3), "r"(b0), "r"(b1));
}

__device__ __forceinline__ unsigned f2h(float lo, float hi) {
    __half2 h = __floats2half2_rn(lo, hi);
    return *(unsigned*)&h;
}

#define CP_COMMIT() asm volatile("cp.async.commit_group;")
#define CP_WAIT0()  asm volatile("cp.async.wait_group 0;")

__device__ __forceinline__ void cp16(float* smdst, const float* gsrc) {
    unsigned sa = (unsigned)__cvta_generic_to_shared(smdst);
    asm volatile("cp.async.cg.shared.global [%0], [%1], 16;" :: "r"(sa), "l"(gsrc));
}

// 128 rows x 32 floats -> [r*LDA + c]
__device__ __forceinline__ void act_cp(float* sm, int dstOff, const float* A,
                                       size_t rowBase, int gld, int kb, int tid) {
#pragma unroll
    for (int i = 0; i < 4; i++) {
        const int idx = tid + THREADS * i;      // 0..1023
        const int r = idx >> 3, q = (idx & 7) * 4;
        cp16(&sm[dstOff + r * LDA + q], A + (rowBase + r) * (size_t)gld + kb + q);
    }
}
template <int NF>
__device__ __forceinline__ void w_cp(float* sm, int dstOff, const float* gsrc, int tid) {
#pragma unroll
    for (int i = tid * 4; i < NF; i += THREADS * 4)
        cp16(&sm[dstOff + i], gsrc + i);
}

// ---------------- prep: fp32 row-major -> frag-major fp16 ----------------
__global__ void __launch_bounds__(256)
lca_prep(const float* __restrict__ Wq, const float* __restrict__ Wk,
         const float* __restrict__ Wv, const float* __restrict__ Wo)
{
    const int idx = blockIdx.x * 256 + threadIdx.x;   // < 327680
    if (idx < 65536) {                                // WqH
        int i = idx;
        int h = i & 7, lane = (i >> 3) & 31, T = (i >> 8) & 15, kc = i >> 12;
        int lm = lane & 3, l4 = lane >> 2;
        int k = kc * 32 + (h >> 1) * 8 + 2 * lm + (h & 1);
        WqH[i] = __float2half_rn(Wq[k * 128 + T * 8 + l4]);
    } else if (idx < 65536 + 98304) {                 // WkH
        int i = idx - 65536;
        int h = i & 7, lane = (i >> 3) & 31, T = (i >> 8) & 15, kc = i >> 12;
        int lm = lane & 3, l4 = lane >> 2;
        int k = kc * 32 + (h >> 1) * 8 + 2 * lm + (h & 1);
        WkH[i] = __float2half_rn(Wk[k * 128 + T * 8 + l4]);
    } else if (idx < 65536 + 2 * 98304) {             // WvH
        int i = idx - 65536 - 98304;
        int h = i & 7, lane = (i >> 3) & 31, T = (i >> 8) & 15, kc = i >> 12;
        int lm = lane & 3, l4 = lane >> 2;
        int k = kc * 32 + (h >> 1) * 8 + 2 * lm + (h & 1);
        WvH[i] = __float2half_rn(Wv[k * 128 + T * 8 + l4]);
    } else {                                          // WoH
        int i = idx - 65536 - 2 * 98304;
        int h = i & 7, lane = (i >> 3) & 31, T = (i >> 8) & 63, c = i >> 14;
        int lm = lane & 3, l4 = lane >> 2;
        int k = c * 32 + (h >> 1) * 8 + 2 * lm + (h & 1);
        WoH[i] = __float2half_rn(Wo[k * 512 + T * 8 + l4]);
    }
}

// ---------------------------------- main ----------------------------------
__global__ void __launch_bounds__(THREADS, 1)
lca_tc(const float* __restrict__ x, const float* __restrict__ ctx,
       const float* __restrict__ bo, const float* __restrict__ g,
       float* __restrict__ out)
{
    extern __shared__ float sm[];
    __half* ph = (__half*)(sm + OFF_PH);
    const int tid  = threadIdx.x;
    const int lane = tid & 31;
    const int warp = tid >> 5;          // 0..7
    const int l4   = lane >> 2;
    const int lm   = lane & 3;
    const int band = warp >> 1;         // A/B: 4 bands x 32 rows
    const int cg   = warp & 1;          //      2 colgrps x 64 cols
    const size_t Rbase = (size_t)blockIdx.x * ROWS;

    for (int i = tid; i < 512; i += THREADS) {
        sm[OFF_BG + i]       = __ldg(&bo[i]);
        sm[OFF_BG + 512 + i] = __ldg(&g[i]);
    }
    if (tid < 64) sm[OFF_N2 + tid] = 0.f;

    // ============== Phase A: q = x @ Wq (16 chunks of 32k) ==============
    {
        float qa[2][8][4];
#pragma unroll
        for (int m = 0; m < 2; m++)
#pragma unroll
            for (int t = 0; t < 8; t++)
#pragma unroll
                for (int j = 0; j < 4; j++) qa[m][t][j] = 0.f;

        act_cp(sm, OFF_ACT, x, Rbase, 512, 0, tid);
        w_cp<2048>(sm, OFF_W, (const float*)WqH, tid);
        CP_COMMIT();

#pragma unroll 1
        for (int c = 0; c < 16; c++) {
            const int cb = c & 1;
            CP_WAIT0();
            __syncthreads();
            if (c + 1 < 16) {
                act_cp(sm, OFF_ACT + (cb ^ 1) * 5120, x, Rbase, 512, (c + 1) * 32, tid);
                w_cp<2048>(sm, OFF_W + (cb ^ 1) * 4096, (const float*)WqH + (c + 1) * 2048, tid);
                CP_COMMIT();
            }
            const float* AB = &sm[OFF_ACT + cb * 5120];
            const uint4* WB = (const uint4*)&sm[OFF_W + cb * 4096];

            unsigned aa[2][2][4];   // [kg][m]
#pragma unroll
            for (int kg = 0; kg < 2; kg++)
#pragma unroll
                for (int m = 0; m < 2; m++) {
                    const float* p = &AB[(band * 32 + m * 16 + l4) * LDA + kg * 16 + 2 * lm];
                    const float2 v0 = *(const float2*)p;
                    const float2 v1 = *(const float2*)(p + 8 * LDA);
                    const float2 v2 = *(const float2*)(p + 8);
                    const float2 v3 = *(const float2*)(p + 8 * LDA + 8);
                    aa[kg][m][0] = f2h(v0.x, v0.y);
                    aa[kg][m][1] = f2h(v1.x, v1.y);
                    aa[kg][m][2] = f2h(v2.x, v2.y);
                    aa[kg][m][3] = f2h(v3.x, v3.y);
                }
#pragma unroll
            for (int t = 0; t < 8; t++) {
                const uint4 Bt = WB[(cg * 8 + t) * 32 + lane];
#pragma unroll
                for (int kg = 0; kg < 2; kg++) {
                    const unsigned b0 = kg ? Bt.z : Bt.x;
                    const unsigned b1 = kg ? Bt.w : Bt.y;
                    mma16(qa[0][t], aa[kg][0][0], aa[kg][0][1], aa[kg][0][2], aa[kg][0][3], b0, b1);
                    mma16(qa[1][t], aa[kg][1][0], aa[kg][1][1], aa[kg][1][2], aa[kg][1][3], b0, b1);
                }
            }
        }

        // issue B chunk0 copies (disjoint buffers), then write q
        act_cp(sm, OFF_ACT, ctx, Rbase, 768, 0, tid);
        w_cp<2048>(sm, OFF_W, (const float*)WkH, tid);
        w_cp<2048>(sm, OFF_W + 2048, (const float*)WvH, tid);
        CP_COMMIT();

#pragma unroll
        for (int m = 0; m < 2; m++) {
            const int rA = band * 32 + m * 16 + l4;
#pragma unroll
            for (int t = 0; t < 8; t++) {
                const int col = (cg * 8 + t) * 8 + 2 * lm;
                *(float2*)&sm[OFF_Q + rA * LDQ + col]       = make_float2(qa[m][t][0], qa[m][t][1]);
                *(float2*)&sm[OFF_Q + (rA + 8) * LDQ + col] = make_float2(qa[m][t][2], qa[m][t][3]);
            }
        }
    }
    __syncthreads();

    // softmax per (row, head), *scale, in place (512 tasks)
#pragma unroll 1
    for (int task = tid; task < ROWS * 4; task += THREADS) {
        const int r = task >> 2, h = task & 3;
        float* qp = &sm[OFF_Q + r * LDQ + h * 32];
        float mx = qp[0];
#pragma unroll
        for (int i = 1; i < 32; i++) mx = fmaxf(mx, qp[i]);
        float s = 0.f;
#pragma unroll
        for (int i = 0; i < 32; i++) s += __expf(qp[i] - mx);
        const float inv = 0.17677669529663687f / s;   // 32^-0.5 / sum
#pragma unroll
        for (int i = 0; i < 32; i++) qp[i] = __expf(qp[i] - mx) * inv;
    }

    // ===== Phase B: k=sigmoid(ctx@Wk), v=ctx@Wv, s=q.k, P=s*v (24 chunks) =====
    {
        float ka[2][8][4], va[2][8][4];
#pragma unroll
        for (int m = 0; m < 2; m++)
#pragma unroll
            for (int t = 0; t < 8; t++)
#pragma unroll
                for (int j = 0; j < 4; j++) { ka[m][t][j] = 0.f; va[m][t][j] = 0.f; }

#pragma unroll 1
        for (int c = 0; c < 24; c++) {
            const int cb = c & 1;
            CP_WAIT0();
            __syncthreads();
            if (c + 1 < 24) {
                act_cp(sm, OFF_ACT + (cb ^ 1) * 5120, ctx, Rbase, 768, (c + 1) * 32, tid);
                w_cp<2048>(sm, OFF_W + (cb ^ 1) * 4096, (const float*)WkH + (c + 1) * 2048, tid);
                w_cp<2048>(sm, OFF_W + (cb ^ 1) * 4096 + 2048, (const float*)WvH + (c + 1) * 2048, tid);
                CP_COMMIT();
            }
            const float* AB = &sm[OFF_ACT + cb * 5120];
            const uint4* KB = (const uint4*)&sm[OFF_W + cb * 4096];
            const uint4* VB = (const uint4*)&sm[OFF_W + cb * 4096 + 2048];

            unsigned aa[2][2][4];
#pragma unroll
            for (int kg = 0; kg < 2; kg++)
#pragma unroll
                for (int m = 0; m < 2; m++) {
                    const float* p = &AB[(band * 32 + m * 16 + l4) * LDA + kg * 16 + 2 * lm];
                    const float2 v0 = *(const float2*)p;
                    const float2 v1 = *(const float2*)(p + 8 * LDA);
                    const float2 v2 = *(const float2*)(p + 8);
                    const float2 v3 = *(const float2*)(p + 8 * LDA + 8);
                    aa[kg][m][0] = f2h(v0.x, v0.y);
                    aa[kg][m][1] = f2h(v1.x, v1.y);
                    aa[kg][m][2] = f2h(v2.x, v2.y);
                    aa[kg][m][3] = f2h(v3.x, v3.y);
                }
#pragma unroll
            for (int t = 0; t < 8; t++) {
                const uint4 BtK = KB[(cg * 8 + t) * 32 + lane];
                const uint4 BtV = VB[(cg * 8 + t) * 32 + lane];
#pragma unroll
                for (int kg = 0; kg < 2; kg++) {
                    unsigned b0 = kg ? BtK.z : BtK.x;
                    unsigned b1 = kg ? BtK.w : BtK.y;
                    mma16(ka[0][t], aa[kg][0][0], aa[kg][0][1], aa[kg][0][2], aa[kg][0][3], b0, b1);
                    mma16(ka[1][t], aa[kg][1][0], aa[kg][1][1], aa[kg][1][2], aa[kg][1][3], b0, b1);
                    b0 = kg ? BtV.z : BtV.x;
                    b1 = kg ? BtV.w : BtV.y;
                    mma16(va[0][t], aa[kg][0][0], aa[kg][0][1], aa[kg][0][2], aa[kg][0][3], b0, b1);
                    mma16(va[1][t], aa[kg][1][0], aa[kg][1][1], aa[kg][1][2], aa[kg][1][3], b0, b1);
                }
            }
        }

        // epilogue part 1: s = q . sigmoid(k) per (row, head=cg*2+(t>>2)) — reads q
        float d0v[2][2], d1v[2][2];
#pragma unroll
        for (int m = 0; m < 2; m++) {
            const int rA = band * 32 + m * 16 + l4;
            float d0[2] = {0.f, 0.f}, d1[2] = {0.f, 0.f};
#pragma unroll
            for (int t = 0; t < 8; t++) {
                const int hh = t >> 2;
                const int col = (cg * 8 + t) * 8 + 2 * lm;
                const float2 q1 = *(const float2*)&sm[OFF_Q + rA * LDQ + col];
                const float2 q2 = *(const float2*)&sm[OFF_Q + (rA + 8) * LDQ + col];
                d0[hh] += q1.x / (1.f + __expf(-ka[m][t][0])) + q1.y / (1.f + __expf(-ka[m][t][1]));
                d1[hh] += q2.x / (1.f + __expf(-ka[m][t][2])) + q2.y / (1.f + __expf(-ka[m][t][3]));
            }
#pragma unroll
            for (int hh = 0; hh < 2; hh++) {
                d0[hh] += __shfl_xor_sync(0xffffffffu, d0[hh], 1);
                d0[hh] += __shfl_xor_sync(0xffffffffu, d0[hh], 2);
                d1[hh] += __shfl_xor_sync(0xffffffffu, d1[hh], 1);
                d1[hh] += __shfl_xor_sync(0xffffffffu, d1[hh], 2);
                d0v[m][hh] = d0[hh]; d1v[m][hh] = d1[hh];
            }
        }
        __syncthreads();   // all q reads done; OFF_Q free for Wo staging

        // stage Wo chunk0 into OFF_WO buffer0 (overlays q region)
        w_cp<8192>(sm, OFF_WO, (const float*)WoH, tid);
        CP_COMMIT();

        // epilogue part 2: P = s*v as half2
#pragma unroll
        for (int m = 0; m < 2; m++) {
            const int rA = band * 32 + m * 16 + l4;
#pragma unroll
            for (int t = 0; t < 8; t++) {
                const int hh = t >> 2;
                const int col = (cg * 8 + t) * 8 + 2 * lm;
                *(__half2*)&ph[rA * LDPH + col] =
                    __floats2half2_rn(d0v[m][hh] * va[m][t][0], d0v[m][hh] * va[m][t][1]);
                *(__half2*)&ph[(rA + 8) * LDPH + col] =
                    __floats2half2_rn(d1v[m][hh] * va[m][t][2], d1v[m][hh] * va[m][t][3]);
            }
        }
    }

    // ===== Phase C: y = P @ Wo + bo, fused RMSNorm; 2 subpasses of 64 rows =====
    const int band2 = warp >> 2;   // 2 bands x 32 rows
    const int cg2   = warp & 3;    // 4 colgrps x 128 cols
#pragma unroll 1
    for (int sp = 0; sp < 2; sp++) {
        float facc[2][16][4];
#pragma unroll
        for (int m = 0; m < 2; m++)
#pragma unroll
            for (int t = 0; t < 16; t++)
#pragma unroll
                for (int j = 0; j < 4; j++) facc[m][t][j] = 0.f;

#pragma unroll 1
        for (int c = 0; c < 4; c++) {
            const int cb = c & 1;
            CP_WAIT0();
            __syncthreads();
            if (!(sp == 1 && c == 3)) {
                const int nc = (c + 1) & 3;
                w_cp<8192>(sm, OFF_WO + (cb ^ 1) * 8192, (const float*)WoH + nc * 8192, tid);
                CP_COMMIT();
            }
            const uint4* WOB = (const uint4*)&sm[OFF_WO + cb * 8192];

            unsigned aa[2][2][4];   // [kg][m]
#pragma unroll
            for (int kg = 0; kg < 2; kg++)
#pragma unroll
                for (int m = 0; m < 2; m++) {
                    const int row = sp * 64 + band2 * 32 + m * 16 + l4;
                    const __half* pp = &ph[row * LDPH + (c * 2 + kg) * 16 + 2 * lm];
                    aa[kg][m][0] = *(const unsigned*)&pp[0];
                    aa[kg][m][1] = *(const unsigned*)&pp[8 * LDPH];
                    aa[kg][m][2] = *(const unsigned*)&pp[8];
                    aa[kg][m][3] = *(const unsigned*)&pp[8 * LDPH + 8];
                }
#pragma unroll
            for (int t = 0; t < 16; t++) {
                const uint4 Bt = WOB[(cg2 * 16 + t) * 32 + lane];
#pragma unroll
                for (int kg = 0; kg < 2; kg++) {
                    const unsigned b0 = kg ? Bt.z : Bt.x;
                    const unsigned b1 = kg ? Bt.w : Bt.y;
                    mma16(facc[0][t], aa[kg][0][0], aa[kg][0][1], aa[kg][0][2], aa[kg][0][3], b0, b1);
                    mma16(facc[1][t], aa[kg][1][0], aa[kg][1][1], aa[kg][1][2], aa[kg][1][3], b0, b1);
                }
            }
        }

        // epilogue: +bo, row sumsq, norm, scale, store
        float ssA[2] = {0.f, 0.f}, ssB[2] = {0.f, 0.f};
#pragma unroll
        for (int m = 0; m < 2; m++)
#pragma unroll
            for (int t = 0; t < 16; t++) {
                const int col = cg2 * 128 + t * 8 + 2 * lm;
                const float2 b2 = *(const float2*)&sm[OFF_BG + col];
                facc[m][t][0] += b2.x; facc[m][t][1] += b2.y;
                facc[m][t][2] += b2.x; facc[m][t][3] += b2.y;
                ssA[m] += facc[m][t][0] * facc[m][t][0] + facc[m][t][1] * facc[m][t][1];
                ssB[m] += facc[m][t][2] * facc[m][t][2] + facc[m][t][3] * facc[m][t][3];
            }
#pragma unroll
        for (int m = 0; m < 2; m++) {
            ssA[m] += __shfl_xor_sync(0xffffffffu, ssA[m], 1);
            ssA[m] += __shfl_xor_sync(0xffffffffu, ssA[m], 2);
            ssB[m] += __shfl_xor_sync(0xffffffffu, ssB[m], 1);
            ssB[m] += __shfl_xor_sync(0xffffffffu, ssB[m], 2);
            if (lm == 0) {
                atomicAdd(&sm[OFF_N2 + band2 * 32 + m * 16 + l4], ssA[m]);
                atomicAdd(&sm[OFF_N2 + band2 * 32 + m * 16 + l4 + 8], ssB[m]);
            }
        }
        __syncthreads();
        if (tid < 64) {
            sm[OFF_RS + tid] = 22.627416997969522f / fmaxf(sqrtf(sm[OFF_N2 + tid]), 1e-12f);
            sm[OFF_N2 + tid] = 0.f;
        }
        __syncthreads();

#pragma unroll
        for (int m = 0; m < 2; m++) {
            const int rloc = band2 * 32 + m * 16 + l4;
            const float cA = sm[OFF_RS + rloc], cB = sm[OFF_RS + rloc + 8];
            const size_t gr = (Rbase + sp * 64 + rloc) * 512;
#pragma unroll
            for (int t = 0; t < 16; t++) {
                const int col = cg2 * 128 + t * 8 + 2 * lm;
                const float2 g2 = *(const float2*)&sm[OFF_BG + 512 + col];
                *(float2*)&out[gr + col] =
                    make_float2(facc[m][t][0] * cA * g2.x, facc[m][t][1] * cA * g2.y);
                *(float2*)&out[gr + 8 * 512 + col] =
                    make_float2(facc[m][t][2] * cB * g2.x, facc[m][t][3] * cB * g2.y);
            }
        }
    }
}

extern "C" void kernel_launch(void* const* d_in, const int* in_sizes, int n_in,
                              void* d_out, int out_size)
{
    const float* x   = (const float*)d_in[0];
    const float* ctx = (const float*)d_in[1];
    const float* Wq  = (const float*)d_in[2];
    const float* Wk  = (const float*)d_in[3];
    const float* Wv  = (const float*)d_in[4];
    const float* Wo  = (const float*)d_in[5];
    const float* bo  = (const float*)d_in[6];
    const float* g   = (const float*)d_in[7];
    float* out = (float*)d_out;

    const int B = in_sizes[0] / 512;   // 65536
    const size_t SMEM = (size_t)SMEM_FLOATS * sizeof(float);   // 180736 B

    lca_prep<<<1280, 256>>>(Wq, Wk, Wv, Wo);

    cudaFuncSetAttribute(lca_tc, cudaFuncAttributeMaxDynamicSharedMemorySize, (int)SMEM);
    lca_tc<<<B / ROWS, THREADS, SMEM>>>(x, ctx, bo, g, out);
}

// round 12
// speedup vs baseline: 1.6577x; 1.0641x over previous
#include <cuda_runtime.h>
#include <cuda_fp16.h>
#include <math.h>
#include <stdint.h>

#define THREADS 256
#define ROWS 128
#define LDA 40     // act smem row stride (32+8): conflict-free LDS.64 A-frags
#define LDQ 132    // q fp32 stride
#define LDPH 136   // P half stride

// smem float offsets
#define OFF_Q   0        // q fp32 128*132 = 16896 ; phase C: Wo 2 x 8192 overlays
#define OFF_WO  0
#define OFF_PH  16896    // P half: 128*136 halves = 8704 floats
#define OFF_ACT 25600    // 3 x 5120 = 15360
#define OFF_W   40960    // 3 x 4096 = 12288
#define OFF_BG  53248    // bo 512 | g 512
#define OFF_N2  54272    // 64
#define OFF_RS  54336    // 64
#define SMEM_FLOATS 54400   // 217600 bytes

// frag-major fp16 weights: proj [kc][T16][lane][8h], Wo [c][T64][lane][8h]
__device__ __half WqH[16 * 4096];
__device__ __half WkH[24 * 4096];
__device__ __half WvH[24 * 4096];
__device__ __half WoH[4 * 16384];

__device__ __forceinline__ void mma16(float* d, unsigned a0, unsigned a1, unsigned a2,
                                      unsigned a3, unsigned b0, unsigned b1) {
    asm volatile(
        "mma.sync.aligned.m16n8k16.row.col.f32.f16.f16.f32 "
        "{%0,%1,%2,%3},{%4,%5,%6,%7},{%8,%9},{%0,%1,%2,%3};"
        : "+f"(d[0]), "+f"(d[1]), "+f"(d[2]), "+f"(d[3])
        : "r"(a0), "r"(a1), "r"(a2), "r"(a3), "r"(b0), "r"(b1));
}

__device__ __forceinline__ unsigned f2h(float lo, float hi) {
    __half2 h = __floats2half2_rn(lo, hi);
    return *(unsigned*)&h;
}

#define CP_COMMIT() asm volatile("cp.async.commit_group;")
#define CP_WAIT0()  asm volatile("cp.async.wait_group 0;")
#define CP_WAIT1()  asm volatile("cp.async.wait_group 1;")

__device__ __forceinline__ void cp16(float* smdst, const float* gsrc) {
    unsigned sa = (unsigned)__cvta_generic_to_shared(smdst);
    asm volatile("cp.async.cg.shared.global [%0], [%1], 16;" :: "r"(sa), "l"(gsrc));
}

// 128 rows x 32 floats -> [r*LDA + c]
__device__ __forceinline__ void act_cp(float* sm, int dstOff, const float* A,
                                       size_t rowBase, int gld, int kb, int tid) {
#pragma unroll
    for (int i = 0; i < 4; i++) {
        const int idx = tid + THREADS * i;      // 0..1023
        const int r = idx >> 3, q = (idx & 7) * 4;
        cp16(&sm[dstOff + r * LDA + q], A + (rowBase + r) * (size_t)gld + kb + q);
    }
}
template <int NF>
__device__ __forceinline__ void w_cp(float* sm, int dstOff, const float* gsrc, int tid) {
#pragma unroll
    for (int i = tid * 4; i < NF; i += THREADS * 4)
        cp16(&sm[dstOff + i], gsrc + i);
}

// unified A+B stream: chunks 0..15 = (x, Wq); 16..39 = (ctx, Wk+Wv)
__device__ __forceinline__ void issue_chunk(float* sm, int c, const float* x,
                                            const float* ctx, size_t Rbase, int tid) {
    const int st = c % 3;
    if (c < 16) {
        act_cp(sm, OFF_ACT + st * 5120, x, Rbase, 512, c * 32, tid);
        w_cp<2048>(sm, OFF_W + st * 4096, (const float*)WqH + c * 2048, tid);
    } else {
        const int cb = c - 16;
        act_cp(sm, OFF_ACT + st * 5120, ctx, Rbase, 768, cb * 32, tid);
        w_cp<2048>(sm, OFF_W + st * 4096, (const float*)WkH + cb * 2048, tid);
        w_cp<2048>(sm, OFF_W + st * 4096 + 2048, (const float*)WvH + cb * 2048, tid);
    }
    CP_COMMIT();
}

// ---------------- prep: fp32 row-major -> frag-major fp16 ----------------
__global__ void __launch_bounds__(256)
lca_prep(const float* __restrict__ Wq, const float* __restrict__ Wk,
         const float* __restrict__ Wv, const float* __restrict__ Wo)
{
    const int idx = blockIdx.x * 256 + threadIdx.x;   // < 327680
    if (idx < 65536) {                                // WqH
        int i = idx;
        int h = i & 7, lane = (i >> 3) & 31, T = (i >> 8) & 15, kc = i >> 12;
        int lm = lane & 3, l4 = lane >> 2;
        int k = kc * 32 + (h >> 1) * 8 + 2 * lm + (h & 1);
        WqH[i] = __float2half_rn(Wq[k * 128 + T * 8 + l4]);
    } else if (idx < 65536 + 98304) {                 // WkH
        int i = idx - 65536;
        int h = i & 7, lane = (i >> 3) & 31, T = (i >> 8) & 15, kc = i >> 12;
        int lm = lane & 3, l4 = lane >> 2;
        int k = kc * 32 + (h >> 1) * 8 + 2 * lm + (h & 1);
        WkH[i] = __float2half_rn(Wk[k * 128 + T * 8 + l4]);
    } else if (idx < 65536 + 2 * 98304) {             // WvH
        int i = idx - 65536 - 98304;
        int h = i & 7, lane = (i >> 3) & 31, T = (i >> 8) & 15, kc = i >> 12;
        int lm = lane & 3, l4 = lane >> 2;
        int k = kc * 32 + (h >> 1) * 8 + 2 * lm + (h & 1);
        WvH[i] = __float2half_rn(Wv[k * 128 + T * 8 + l4]);
    } else {                                          // WoH
        int i = idx - 65536 - 2 * 98304;
        int h = i & 7, lane = (i >> 3) & 31, T = (i >> 8) & 63, c = i >> 14;
        int lm = lane & 3, l4 = lane >> 2;
        int k = c * 32 + (h >> 1) * 8 + 2 * lm + (h & 1);
        WoH[i] = __float2half_rn(Wo[k * 512 + T * 8 + l4]);
    }
}

// ---------------------------------- main ----------------------------------
__global__ void __launch_bounds__(THREADS, 1)
lca_tc(const float* __restrict__ x, const float* __restrict__ ctx,
       const float* __restrict__ bo, const float* __restrict__ g,
       float* __restrict__ out)
{
    extern __shared__ float sm[];
    __half* ph = (__half*)(sm + OFF_PH);
    const int tid  = threadIdx.x;
    const int lane = tid & 31;
    const int warp = tid >> 5;          // 0..7
    const int l4   = lane >> 2;
    const int lm   = lane & 3;
    const int band = warp >> 1;         // A/B: 4 bands x 32 rows
    const int cg   = warp & 1;          //      2 colgrps x 64 cols
    const size_t Rbase = (size_t)blockIdx.x * ROWS;

    for (int i = tid; i < 512; i += THREADS) {
        sm[OFF_BG + i]       = __ldg(&bo[i]);
        sm[OFF_BG + 512 + i] = __ldg(&g[i]);
    }
    if (tid < 64) sm[OFF_N2 + tid] = 0.f;

    // prologue: chunks 0, 1 in flight
    issue_chunk(sm, 0, x, ctx, Rbase, tid);
    issue_chunk(sm, 1, x, ctx, Rbase, tid);

    // ============== Phase A: q = x @ Wq (chunks 0..15) ==============
    {
        float qa[2][8][4];
#pragma unroll
        for (int m = 0; m < 2; m++)
#pragma unroll
            for (int t = 0; t < 8; t++)
#pragma unroll
                for (int j = 0; j < 4; j++) qa[m][t][j] = 0.f;

#pragma unroll 1
        for (int c = 0; c < 16; c++) {
            const int st = c % 3;
            CP_WAIT1();
            __syncthreads();
            issue_chunk(sm, c + 2, x, ctx, Rbase, tid);   // c+2 <= 17, always valid
            const float* AB = &sm[OFF_ACT + st * 5120];
            const uint4* WB = (const uint4*)&sm[OFF_W + st * 4096];

            unsigned aa[2][2][4];   // [kg][m]
#pragma unroll
            for (int kg = 0; kg < 2; kg++)
#pragma unroll
                for (int m = 0; m < 2; m++) {
                    const float* p = &AB[(band * 32 + m * 16 + l4) * LDA + kg * 16 + 2 * lm];
                    const float2 v0 = *(const float2*)p;
                    const float2 v1 = *(const float2*)(p + 8 * LDA);
                    const float2 v2 = *(const float2*)(p + 8);
                    const float2 v3 = *(const float2*)(p + 8 * LDA + 8);
                    aa[kg][m][0] = f2h(v0.x, v0.y);
                    aa[kg][m][1] = f2h(v1.x, v1.y);
                    aa[kg][m][2] = f2h(v2.x, v2.y);
                    aa[kg][m][3] = f2h(v3.x, v3.y);
                }
#pragma unroll
            for (int t = 0; t < 8; t++) {
                const uint4 Bt = WB[(cg * 8 + t) * 32 + lane];
#pragma unroll
                for (int kg = 0; kg < 2; kg++) {
                    const unsigned b0 = kg ? Bt.z : Bt.x;
                    const unsigned b1 = kg ? Bt.w : Bt.y;
                    mma16(qa[0][t], aa[kg][0][0], aa[kg][0][1], aa[kg][0][2], aa[kg][0][3], b0, b1);
                    mma16(qa[1][t], aa[kg][1][0], aa[kg][1][1], aa[kg][1][2], aa[kg][1][3], b0, b1);
                }
            }
        }

        // store raw q (B chunks 16,17 already in flight)
#pragma unroll
        for (int m = 0; m < 2; m++) {
            const int rA = band * 32 + m * 16 + l4;
#pragma unroll
            for (int t = 0; t < 8; t++) {
                const int col = (cg * 8 + t) * 8 + 2 * lm;
                *(float2*)&sm[OFF_Q + rA * LDQ + col]       = make_float2(qa[m][t][0], qa[m][t][1]);
                *(float2*)&sm[OFF_Q + (rA + 8) * LDQ + col] = make_float2(qa[m][t][2], qa[m][t][3]);
            }
        }
    }
    __syncthreads();

    // softmax per (row, head), *scale, in place (512 tasks)
#pragma unroll 1
    for (int task = tid; task < ROWS * 4; task += THREADS) {
        const int r = task >> 2, h = task & 3;
        float* qp = &sm[OFF_Q + r * LDQ + h * 32];
        float mx = qp[0];
#pragma unroll
        for (int i = 1; i < 32; i++) mx = fmaxf(mx, qp[i]);
        float s = 0.f;
#pragma unroll
        for (int i = 0; i < 32; i++) s += __expf(qp[i] - mx);
        const float inv = 0.17677669529663687f / s;   // 32^-0.5 / sum
#pragma unroll
        for (int i = 0; i < 32; i++) qp[i] = __expf(qp[i] - mx) * inv;
    }

    // ===== Phase B: k=sigmoid(ctx@Wk), v=ctx@Wv, s=q.k, P=s*v (chunks 16..39) =====
    {
        float ka[2][8][4], va[2][8][4];
#pragma unroll
        for (int m = 0; m < 2; m++)
#pragma unroll
            for (int t = 0; t < 8; t++)
#pragma unroll
                for (int j = 0; j < 4; j++) { ka[m][t][j] = 0.f; va[m][t][j] = 0.f; }

#pragma unroll 1
        for (int c = 16; c < 40; c++) {
            const int st = c % 3;
            if (c == 39) { CP_WAIT0(); } else { CP_WAIT1(); }
            __syncthreads();
            if (c + 2 < 40) issue_chunk(sm, c + 2, x, ctx, Rbase, tid);
            const float* AB = &sm[OFF_ACT + st * 5120];
            const uint4* KB = (const uint4*)&sm[OFF_W + st * 4096];
            const uint4* VB = (const uint4*)&sm[OFF_W + st * 4096 + 2048];

            unsigned aa[2][2][4];
#pragma unroll
            for (int kg = 0; kg < 2; kg++)
#pragma unroll
                for (int m = 0; m < 2; m++) {
                    const float* p = &AB[(band * 32 + m * 16 + l4) * LDA + kg * 16 + 2 * lm];
                    const float2 v0 = *(const float2*)p;
                    const float2 v1 = *(const float2*)(p + 8 * LDA);
                    const float2 v2 = *(const float2*)(p + 8);
                    const float2 v3 = *(const float2*)(p + 8 * LDA + 8);
                    aa[kg][m][0] = f2h(v0.x, v0.y);
                    aa[kg][m][1] = f2h(v1.x, v1.y);
                    aa[kg][m][2] = f2h(v2.x, v2.y);
                    aa[kg][m][3] = f2h(v3.x, v3.y);
                }
#pragma unroll
            for (int t = 0; t < 8; t++) {
                const uint4 BtK = KB[(cg * 8 + t) * 32 + lane];
                const uint4 BtV = VB[(cg * 8 + t) * 32 + lane];
#pragma unroll
                for (int kg = 0; kg < 2; kg++) {
                    unsigned b0 = kg ? BtK.z : BtK.x;
                    unsigned b1 = kg ? BtK.w : BtK.y;
                    mma16(ka[0][t], aa[kg][0][0], aa[kg][0][1], aa[kg][0][2], aa[kg][0][3], b0, b1);
                    mma16(ka[1][t], aa[kg][1][0], aa[kg][1][1], aa[kg][1][2], aa[kg][1][3], b0, b1);
                    b0 = kg ? BtV.z : BtV.x;
                    b1 = kg ? BtV.w : BtV.y;
                    mma16(va[0][t], aa[kg][0][0], aa[kg][0][1], aa[kg][0][2], aa[kg][0][3], b0, b1);
                    mma16(va[1][t], aa[kg][1][0], aa[kg][1][1], aa[kg][1][2], aa[kg][1][3], b0, b1);
                }
            }
        }

        // epilogue part 1: s = q . sigmoid(k) per (row, head=cg*2+(t>>2))
        float d0v[2][2], d1v[2][2];
#pragma unroll
        for (int m = 0; m < 2; m++) {
            const int rA = band * 32 + m * 16 + l4;
            float d0[2] = {0.f, 0.f}, d1[2] = {0.f, 0.f};
#pragma unroll
            for (int t = 0; t < 8; t++) {
                const int hh = t >> 2;
                const int col = (cg * 8 + t) * 8 + 2 * lm;
                const float2 q1 = *(const float2*)&sm[OFF_Q + rA * LDQ + col];
                const float2 q2 = *(const float2*)&sm[OFF_Q + (rA + 8) * LDQ + col];
                d0[hh] += q1.x / (1.f + __expf(-ka[m][t][0])) + q1.y / (1.f + __expf(-ka[m][t][1]));
                d1[hh] += q2.x / (1.f + __expf(-ka[m][t][2])) + q2.y / (1.f + __expf(-ka[m][t][3]));
            }
#pragma unroll
            for (int hh = 0; hh < 2; hh++) {
                d0[hh] += __shfl_xor_sync(0xffffffffu, d0[hh], 1);
                d0[hh] += __shfl_xor_sync(0xffffffffu, d0[hh], 2);
                d1[hh] += __shfl_xor_sync(0xffffffffu, d1[hh], 1);
                d1[hh] += __shfl_xor_sync(0xffffffffu, d1[hh], 2);
                d0v[m][hh] = d0[hh]; d1v[m][hh] = d1[hh];
            }
        }
        __syncthreads();   // q reads done; OFF_Q free for Wo staging

        w_cp<8192>(sm, OFF_WO, (const float*)WoH, tid);
        CP_COMMIT();

        // epilogue part 2: P = s*v as half2
#pragma unroll
        for (int m = 0; m < 2; m++) {
            const int rA = band * 32 + m * 16 + l4;
#pragma unroll
            for (int t = 0; t < 8; t++) {
                const int hh = t >> 2;
                const int col = (cg * 8 + t) * 8 + 2 * lm;
                *(__half2*)&ph[rA * LDPH + col] =
                    __floats2half2_rn(d0v[m][hh] * va[m][t][0], d0v[m][hh] * va[m][t][1]);
                *(__half2*)&ph[(rA + 8) * LDPH + col] =
                    __floats2half2_rn(d1v[m][hh] * va[m][t][2], d1v[m][hh] * va[m][t][3]);
            }
        }
    }

    // ===== Phase C: y = P @ Wo + bo, fused RMSNorm; 2 subpasses of 64 rows =====
    const int band2 = warp >> 2;   // 2 bands x 32 rows
    const int cg2   = warp & 3;    // 4 colgrps x 128 cols
#pragma unroll 1
    for (int sp = 0; sp < 2; sp++) {
        float facc[2][16][4];
#pragma unroll
        for (int m = 0; m < 2; m++)
#pragma unroll
            for (int t = 0; t < 16; t++)
#pragma unroll
                for (int j = 0; j < 4; j++) facc[m][t][j] = 0.f;

#pragma unroll 1
        for (int c = 0; c < 4; c++) {
            const int cb = c & 1;
            CP_WAIT0();
            __syncthreads();
            if (!(sp == 1 && c == 3)) {
                const int nc = (c + 1) & 3;
                w_cp<8192>(sm, OFF_WO + (cb ^ 1) * 8192, (const float*)WoH + nc * 8192, tid);
                CP_COMMIT();
            }
            const uint4* WOB = (const uint4*)&sm[OFF_WO + cb * 8192];

            unsigned aa[2][2][4];   // [kg][m]
#pragma unroll
            for (int kg = 0; kg < 2; kg++)
#pragma unroll
                for (int m = 0; m < 2; m++) {
                    const int row = sp * 64 + band2 * 32 + m * 16 + l4;
                    const __half* pp = &ph[row * LDPH + (c * 2 + kg) * 16 + 2 * lm];
                    aa[kg][m][0] = *(const unsigned*)&pp[0];
                    aa[kg][m][1] = *(const unsigned*)&pp[8 * LDPH];
                    aa[kg][m][2] = *(const unsigned*)&pp[8];
                    aa[kg][m][3] = *(const unsigned*)&pp[8 * LDPH + 8];
                }
#pragma unroll
            for (int t = 0; t < 16; t++) {
                const uint4 Bt = WOB[(cg2 * 16 + t) * 32 + lane];
#pragma unroll
                for (int kg = 0; kg < 2; kg++) {
                    const unsigned b0 = kg ? Bt.z : Bt.x;
                    const unsigned b1 = kg ? Bt.w : Bt.y;
                    mma16(facc[0][t], aa[kg][0][0], aa[kg][0][1], aa[kg][0][2], aa[kg][0][3], b0, b1);
                    mma16(facc[1][t], aa[kg][1][0], aa[kg][1][1], aa[kg][1][2], aa[kg][1][3], b0, b1);
                }
            }
        }

        // epilogue: +bo, row sumsq, norm, scale, store
        float ssA[2] = {0.f, 0.f}, ssB[2] = {0.f, 0.f};
#pragma unroll
        for (int m = 0; m < 2; m++)
#pragma unroll
            for (int t = 0; t < 16; t++) {
                const int col = cg2 * 128 + t * 8 + 2 * lm;
                const float2 b2 = *(const float2*)&sm[OFF_BG + col];
                facc[m][t][0] += b2.x; facc[m][t][1] += b2.y;
                facc[m][t][2] += b2.x; facc[m][t][3] += b2.y;
                ssA[m] += facc[m][t][0] * facc[m][t][0] + facc[m][t][1] * facc[m][t][1];
                ssB[m] += facc[m][t][2] * facc[m][t][2] + facc[m][t][3] * facc[m][t][3];
            }
#pragma unroll
        for (int m = 0; m < 2; m++) {
            ssA[m] += __shfl_xor_sync(0xffffffffu, ssA[m], 1);
            ssA[m] += __shfl_xor_sync(0xffffffffu, ssA[m], 2);
            ssB[m] += __shfl_xor_sync(0xffffffffu, ssB[m], 1);
            ssB[m] += __shfl_xor_sync(0xffffffffu, ssB[m], 2);
            if (lm == 0) {
                atomicAdd(&sm[OFF_N2 + band2 * 32 + m * 16 + l4], ssA[m]);
                atomicAdd(&sm[OFF_N2 + band2 * 32 + m * 16 + l4 + 8], ssB[m]);
            }
        }
        __syncthreads();
        if (tid < 64) {
            sm[OFF_RS + tid] = 22.627416997969522f / fmaxf(sqrtf(sm[OFF_N2 + tid]), 1e-12f);
            sm[OFF_N2 + tid] = 0.f;
        }
        __syncthreads();

#pragma unroll
        for (int m = 0; m < 2; m++) {
            const int rloc = band2 * 32 + m * 16 + l4;
            const float cA = sm[OFF_RS + rloc], cB = sm[OFF_RS + rloc + 8];
            const size_t gr = (Rbase + sp * 64 + rloc) * 512;
#pragma unroll
            for (int t = 0; t < 16; t++) {
                const int col = cg2 * 128 + t * 8 + 2 * lm;
                const float2 g2 = *(const float2*)&sm[OFF_BG + 512 + col];
                *(float2*)&out[gr + col] =
                    make_float2(facc[m][t][0] * cA * g2.x, facc[m][t][1] * cA * g2.y);
                *(float2*)&out[gr + 8 * 512 + col] =
                    make_float2(facc[m][t][2] * cB * g2.x, facc[m][t][3] * cB * g2.y);
            }
        }
    }
}

extern "C" void kernel_launch(void* const* d_in, const int* in_sizes, int n_in,
                              void* d_out, int out_size)
{
    const float* x   = (const float*)d_in[0];
    const float* ctx = (const float*)d_in[1];
    const float* Wq  = (const float*)d_in[2];
    const float* Wk  = (const float*)d_in[3];
    const float* Wv  = (const float*)d_in[4];
    const float* Wo  = (const float*)d_in[5];
    const float* bo  = (const float*)d_in[6];
    const float* g   = (const float*)d_in[7];
    float* out = (float*)d_out;

    const int B = in_sizes[0] / 512;   // 65536
    const size_t SMEM = (size_t)SMEM_FLOATS * sizeof(float);   // 217600 B

    lca_prep<<<1280, 256>>>(Wq, Wk, Wv, Wo);

    cudaFuncSetAttribute(lca_tc, cudaFuncAttributeMaxDynamicSharedMemorySize, (int)SMEM);
    lca_tc<<<B / ROWS, THREADS, SMEM>>>(x, ctx, bo, g, out);
}

// round 13
// speedup vs baseline: 1.8206x; 1.0983x over previous
#include <cuda_runtime.h>
#include <cuda_fp16.h>
#include <math.h>
#include <stdint.h>

#define THREADS 256
#define ROWS 128
#define LDA 40     // act smem row stride (32+8)
#define LDPH 136   // P half stride

// smem float offsets
#define OFF_PH  0        // P half: 128*136 halves = 8704 floats
#define OFF_ACT 8704     // 5 x 5120 = 25600 (ends 34304)
#define OFF_W   34304    // 5 x 4096 = 20480 (ends 54784)
#define OFF_WO  8704     // phase C: 2 x 8192 = 16384 (overlays ACT region)
#define OFF_BG  54784    // bo 512 | g 512
#define OFF_N2  55808    // 64
#define OFF_RS  55872    // 64
#define SMEM_FLOATS 55936   // 223744 bytes

// frag-major fp16 weights: proj [kc][T16][lane][8h], Wo [c][T64][lane][8h]
__device__ __half WqH[16 * 4096];
__device__ __half WkH[24 * 4096];
__device__ __half WvH[24 * 4096];
__device__ __half WoH[4 * 16384];

__device__ __forceinline__ void mma16(float* d, unsigned a0, unsigned a1, unsigned a2,
                                      unsigned a3, unsigned b0, unsigned b1) {
    asm volatile(
        "mma.sync.aligned.m16n8k16.row.col.f32.f16.f16.f32 "
        "{%0,%1,%2,%3},{%4,%5,%6,%7},{%8,%9},{%0,%1,%2,%3};"
        : "+f"(d[0]), "+f"(d[1]), "+f"(d[2]), "+f"(d[3])
        : "r"(a0), "r"(a1), "r"(a2), "r"(a3), "r"(b0), "r"(b1));
}

__device__ __forceinline__ unsigned f2h(float lo, float hi) {
    __half2 h = __floats2half2_rn(lo, hi);
    return *(unsigned*)&h;
}

#define CP_COMMIT() asm volatile("cp.async.commit_group;")
#define CP_WAIT0()  asm volatile("cp.async.wait_group 0;")
#define CP_WAIT1()  asm volatile("cp.async.wait_group 1;")

__device__ __forceinline__ void cp16(float* smdst, const float* gsrc) {
    unsigned sa = (unsigned)__cvta_generic_to_shared(smdst);
    asm volatile("cp.async.cg.shared.global [%0], [%1], 16;" :: "r"(sa), "l"(gsrc));
}

// 128 rows x 32 floats -> [r*LDA + c]
__device__ __forceinline__ void act_cp(float* sm, int dstOff, const float* A,
                                       size_t rowBase, int gld, int kb, int tid) {
#pragma unroll
    for (int i = 0; i < 4; i++) {
        const int idx = tid + THREADS * i;
        const int r = idx >> 3, q = (idx & 7) * 4;
        cp16(&sm[dstOff + r * LDA + q], A + (rowBase + r) * (size_t)gld + kb + q);
    }
}
template <int NF>
__device__ __forceinline__ void w_cp(float* sm, int dstOff, const float* gsrc, int tid) {
#pragma unroll
    for (int i = tid * 4; i < NF; i += THREADS * 4)
        cp16(&sm[dstOff + i], gsrc + i);
}

// unified stream: chunks 0..15 = (x, Wq); 16..39 = (ctx, Wk+Wv). 5-stage ring.
__device__ __forceinline__ void issue_chunk(float* sm, int c, const float* x,
                                            const float* ctx, size_t Rbase, int tid) {
    const int st = c % 5;
    if (c < 16) {
        act_cp(sm, OFF_ACT + st * 5120, x, Rbase, 512, c * 32, tid);
        w_cp<2048>(sm, OFF_W + st * 4096, (const float*)WqH + c * 2048, tid);
    } else {
        const int cb = c - 16;
        act_cp(sm, OFF_ACT + st * 5120, ctx, Rbase, 768, cb * 32, tid);
        w_cp<2048>(sm, OFF_W + st * 4096, (const float*)WkH + cb * 2048, tid);
        w_cp<2048>(sm, OFF_W + st * 4096 + 2048, (const float*)WvH + cb * 2048, tid);
    }
    CP_COMMIT();
}

// ---------------- prep: fp32 row-major -> frag-major fp16 ----------------
__global__ void __launch_bounds__(256)
lca_prep(const float* __restrict__ Wq, const float* __restrict__ Wk,
         const float* __restrict__ Wv, const float* __restrict__ Wo)
{
    const int idx = blockIdx.x * 256 + threadIdx.x;   // < 327680
    if (idx < 65536) {
        int i = idx;
        int h = i & 7, lane = (i >> 3) & 31, T = (i >> 8) & 15, kc = i >> 12;
        int lm = lane & 3, l4 = lane >> 2;
        int k = kc * 32 + (h >> 1) * 8 + 2 * lm + (h & 1);
        WqH[i] = __float2half_rn(Wq[k * 128 + T * 8 + l4]);
    } else if (idx < 65536 + 98304) {
        int i = idx - 65536;
        int h = i & 7, lane = (i >> 3) & 31, T = (i >> 8) & 15, kc = i >> 12;
        int lm = lane & 3, l4 = lane >> 2;
        int k = kc * 32 + (h >> 1) * 8 + 2 * lm + (h & 1);
        WkH[i] = __float2half_rn(Wk[k * 128 + T * 8 + l4]);
    } else if (idx < 65536 + 2 * 98304) {
        int i = idx - 65536 - 98304;
        int h = i & 7, lane = (i >> 3) & 31, T = (i >> 8) & 15, kc = i >> 12;
        int lm = lane & 3, l4 = lane >> 2;
        int k = kc * 32 + (h >> 1) * 8 + 2 * lm + (h & 1);
        WvH[i] = __float2half_rn(Wv[k * 128 + T * 8 + l4]);
    } else {
        int i = idx - 65536 - 2 * 98304;
        int h = i & 7, lane = (i >> 3) & 31, T = (i >> 8) & 63, c = i >> 14;
        int lm = lane & 3, l4 = lane >> 2;
        int k = c * 32 + (h >> 1) * 8 + 2 * lm + (h & 1);
        WoH[i] = __float2half_rn(Wo[k * 512 + T * 8 + l4]);
    }
}

// A-fragment load + convert (shared by all phases)
#define LOAD_AFRAGS(AB)                                                          \
    unsigned aa[2][2][4];                                                        \
    {                                                                            \
        _Pragma("unroll")                                                        \
        for (int kg = 0; kg < 2; kg++)                                           \
            _Pragma("unroll")                                                    \
            for (int m = 0; m < 2; m++) {                                        \
                const float* p = &(AB)[(band * 32 + m * 16 + l4) * LDA + kg * 16 + 2 * lm]; \
                const float2 v0 = *(const float2*)p;                             \
                const float2 v1 = *(const float2*)(p + 8 * LDA);                 \
                const float2 v2 = *(const float2*)(p + 8);                       \
                const float2 v3 = *(const float2*)(p + 8 * LDA + 8);             \
                aa[kg][m][0] = f2h(v0.x, v0.y);                                  \
                aa[kg][m][1] = f2h(v1.x, v1.y);                                  \
                aa[kg][m][2] = f2h(v2.x, v2.y);                                  \
                aa[kg][m][3] = f2h(v3.x, v3.y);                                  \
            }                                                                    \
    }

// ---------------------------------- main ----------------------------------
__global__ void __launch_bounds__(THREADS, 1)
lca_tc(const float* __restrict__ x, const float* __restrict__ ctx,
       const float* __restrict__ bo, const float* __restrict__ g,
       float* __restrict__ out)
{
    extern __shared__ float sm[];
    __half* ph = (__half*)(sm + OFF_PH);
    const int tid  = threadIdx.x;
    const int lane = tid & 31;
    const int warp = tid >> 5;          // 0..7
    const int l4   = lane >> 2;
    const int lm   = lane & 3;
    const int band = warp >> 1;         // A/B: 4 bands x 32 rows
    const int cg   = warp & 1;          //      2 colgrps x 64 cols
    const size_t Rbase = (size_t)blockIdx.x * ROWS;

    for (int i = tid; i < 512; i += THREADS) {
        sm[OFF_BG + i]       = __ldg(&bo[i]);
        sm[OFF_BG + 512 + i] = __ldg(&g[i]);
    }
    if (tid < 64) sm[OFF_N2 + tid] = 0.f;

    // pipeline prologue: 3 chunks in flight
    issue_chunk(sm, 0, x, ctx, Rbase, tid);
    issue_chunk(sm, 1, x, ctx, Rbase, tid);
    issue_chunk(sm, 2, x, ctx, Rbase, tid);

    // ============== Phase A: q = x @ Wq (pairs, chunks 0..15) ==============
    float qa[2][8][4];
#pragma unroll
    for (int m = 0; m < 2; m++)
#pragma unroll
        for (int t = 0; t < 8; t++)
#pragma unroll
            for (int j = 0; j < 4; j++) qa[m][t][j] = 0.f;

#pragma unroll 1
    for (int cp = 0; cp < 8; cp++) {
        const int c = 2 * cp;
        CP_WAIT1();
        __syncthreads();
        issue_chunk(sm, c + 3, x, ctx, Rbase, tid);
        issue_chunk(sm, c + 4, x, ctx, Rbase, tid);
#pragma unroll
        for (int sub = 0; sub < 2; sub++) {
            const int cc = c + sub;
            const float* AB = &sm[OFF_ACT + (cc % 5) * 5120];
            const uint4* WB = (const uint4*)&sm[OFF_W + (cc % 5) * 4096];
            LOAD_AFRAGS(AB)
#pragma unroll
            for (int t = 0; t < 8; t++) {
                const uint4 Bt = WB[(cg * 8 + t) * 32 + lane];
#pragma unroll
                for (int kg = 0; kg < 2; kg++) {
                    const unsigned b0 = kg ? Bt.z : Bt.x;
                    const unsigned b1 = kg ? Bt.w : Bt.y;
                    mma16(qa[0][t], aa[kg][0][0], aa[kg][0][1], aa[kg][0][2], aa[kg][0][3], b0, b1);
                    mma16(qa[1][t], aa[kg][1][0], aa[kg][1][1], aa[kg][1][2], aa[kg][1][3], b0, b1);
                }
            }
        }
    }

    // ===== softmax in registers per (row-half, head); pack q -> half2 =====
    __half2 qh[2][8][2];
    {
        const float SCL = 0.17677669529663687f;   // 32^-0.5
#pragma unroll
        for (int m = 0; m < 2; m++)
#pragma unroll
            for (int hh = 0; hh < 2; hh++) {
                float mxA = -1e30f, mxB = -1e30f;
#pragma unroll
                for (int tt = 0; tt < 4; tt++) {
                    const int t = 4 * hh + tt;
                    mxA = fmaxf(mxA, fmaxf(qa[m][t][0], qa[m][t][1]));
                    mxB = fmaxf(mxB, fmaxf(qa[m][t][2], qa[m][t][3]));
                }
                mxA = fmaxf(mxA, __shfl_xor_sync(0xffffffffu, mxA, 1));
                mxA = fmaxf(mxA, __shfl_xor_sync(0xffffffffu, mxA, 2));
                mxB = fmaxf(mxB, __shfl_xor_sync(0xffffffffu, mxB, 1));
                mxB = fmaxf(mxB, __shfl_xor_sync(0xffffffffu, mxB, 2));
                float sA = 0.f, sB = 0.f;
#pragma unroll
                for (int tt = 0; tt < 4; tt++) {
                    const int t = 4 * hh + tt;
                    qa[m][t][0] = __expf(qa[m][t][0] - mxA); sA += qa[m][t][0];
                    qa[m][t][1] = __expf(qa[m][t][1] - mxA); sA += qa[m][t][1];
                    qa[m][t][2] = __expf(qa[m][t][2] - mxB); sB += qa[m][t][2];
                    qa[m][t][3] = __expf(qa[m][t][3] - mxB); sB += qa[m][t][3];
                }
                sA += __shfl_xor_sync(0xffffffffu, sA, 1);
                sA += __shfl_xor_sync(0xffffffffu, sA, 2);
                sB += __shfl_xor_sync(0xffffffffu, sB, 1);
                sB += __shfl_xor_sync(0xffffffffu, sB, 2);
                const float iA = SCL / sA, iB = SCL / sB;
#pragma unroll
                for (int tt = 0; tt < 4; tt++) {
                    const int t = 4 * hh + tt;
                    qh[m][t][0] = __floats2half2_rn(qa[m][t][0] * iA, qa[m][t][1] * iA);
                    qh[m][t][1] = __floats2half2_rn(qa[m][t][2] * iB, qa[m][t][3] * iB);
                }
            }
    }

    // ===== Phase B: k=sigmoid(ctx@Wk), v=ctx@Wv (pairs, chunks 16..39) =====
    {
        float ka[2][8][4], va[2][8][4];
#pragma unroll
        for (int m = 0; m < 2; m++)
#pragma unroll
            for (int t = 0; t < 8; t++)
#pragma unroll
                for (int j = 0; j < 4; j++) { ka[m][t][j] = 0.f; va[m][t][j] = 0.f; }

#pragma unroll 1
        for (int cp = 8; cp < 20; cp++) {
            const int c = 2 * cp;
            if (c + 2 > 39) { CP_WAIT0(); } else { CP_WAIT1(); }
            __syncthreads();
            if (c + 3 <= 39) issue_chunk(sm, c + 3, x, ctx, Rbase, tid);
            if (c + 4 <= 39) issue_chunk(sm, c + 4, x, ctx, Rbase, tid);
#pragma unroll
            for (int sub = 0; sub < 2; sub++) {
                const int cc = c + sub;
                const float* AB = &sm[OFF_ACT + (cc % 5) * 5120];
                const uint4* KB = (const uint4*)&sm[OFF_W + (cc % 5) * 4096];
                const uint4* VB = (const uint4*)&sm[OFF_W + (cc % 5) * 4096 + 2048];
                LOAD_AFRAGS(AB)
#pragma unroll
                for (int t = 0; t < 8; t++) {
                    const uint4 BtK = KB[(cg * 8 + t) * 32 + lane];
                    const uint4 BtV = VB[(cg * 8 + t) * 32 + lane];
#pragma unroll
                    for (int kg = 0; kg < 2; kg++) {
                        unsigned b0 = kg ? BtK.z : BtK.x;
                        unsigned b1 = kg ? BtK.w : BtK.y;
                        mma16(ka[0][t], aa[kg][0][0], aa[kg][0][1], aa[kg][0][2], aa[kg][0][3], b0, b1);
                        mma16(ka[1][t], aa[kg][1][0], aa[kg][1][1], aa[kg][1][2], aa[kg][1][3], b0, b1);
                        b0 = kg ? BtV.z : BtV.x;
                        b1 = kg ? BtV.w : BtV.y;
                        mma16(va[0][t], aa[kg][0][0], aa[kg][0][1], aa[kg][0][2], aa[kg][0][3], b0, b1);
                        mma16(va[1][t], aa[kg][1][0], aa[kg][1][1], aa[kg][1][2], aa[kg][1][3], b0, b1);
                    }
                }
            }
        }

        // epilogue part 1 (registers only): s = q . sigmoid(k)
        float d0v[2][2], d1v[2][2];
#pragma unroll
        for (int m = 0; m < 2; m++) {
            float d0[2] = {0.f, 0.f}, d1[2] = {0.f, 0.f};
#pragma unroll
            for (int t = 0; t < 8; t++) {
                const int hh = t >> 2;
                const float2 q1 = __half22float2(qh[m][t][0]);
                const float2 q2 = __half22float2(qh[m][t][1]);
                d0[hh] += q1.x / (1.f + __expf(-ka[m][t][0])) + q1.y / (1.f + __expf(-ka[m][t][1]));
                d1[hh] += q2.x / (1.f + __expf(-ka[m][t][2])) + q2.y / (1.f + __expf(-ka[m][t][3]));
            }
#pragma unroll
            for (int hh = 0; hh < 2; hh++) {
                d0[hh] += __shfl_xor_sync(0xffffffffu, d0[hh], 1);
                d0[hh] += __shfl_xor_sync(0xffffffffu, d0[hh], 2);
                d1[hh] += __shfl_xor_sync(0xffffffffu, d1[hh], 1);
                d1[hh] += __shfl_xor_sync(0xffffffffu, d1[hh], 2);
                d0v[m][hh] = d0[hh]; d1v[m][hh] = d1[hh];
            }
        }
        __syncthreads();   // all act/W reads done; ACT region free for Wo

        w_cp<8192>(sm, OFF_WO, (const float*)WoH, tid);
        CP_COMMIT();

        // epilogue part 2: P = s*v as half2
#pragma unroll
        for (int m = 0; m < 2; m++) {
            const int rA = band * 32 + m * 16 + l4;
#pragma unroll
            for (int t = 0; t < 8; t++) {
                const int hh = t >> 2;
                const int col = (cg * 8 + t) * 8 + 2 * lm;
                *(__half2*)&ph[rA * LDPH + col] =
                    __floats2half2_rn(d0v[m][hh] * va[m][t][0], d0v[m][hh] * va[m][t][1]);
                *(__half2*)&ph[(rA + 8) * LDPH + col] =
                    __floats2half2_rn(d1v[m][hh] * va[m][t][2], d1v[m][hh] * va[m][t][3]);
            }
        }
    }

    // ===== Phase C: y = P @ Wo + bo, fused RMSNorm; 2 subpasses of 64 rows =====
    const int band2 = warp >> 2;   // 2 bands x 32 rows
    const int cg2   = warp & 3;    // 4 colgrps x 128 cols
#pragma unroll 1
    for (int sp = 0; sp < 2; sp++) {
        float facc[2][16][4];
#pragma unroll
        for (int m = 0; m < 2; m++)
#pragma unroll
            for (int t = 0; t < 16; t++)
#pragma unroll
                for (int j = 0; j < 4; j++) facc[m][t][j] = 0.f;

#pragma unroll 1
        for (int c = 0; c < 4; c++) {
            const int cb = c & 1;
            CP_WAIT0();
            __syncthreads();
            if (!(sp == 1 && c == 3)) {
                const int nc = (c + 1) & 3;
                w_cp<8192>(sm, OFF_WO + (cb ^ 1) * 8192, (const float*)WoH + nc * 8192, tid);
                CP_COMMIT();
            }
            const uint4* WOB = (const uint4*)&sm[OFF_WO + cb * 8192];

            unsigned aa[2][2][4];
#pragma unroll
            for (int kg = 0; kg < 2; kg++)
#pragma unroll
                for (int m = 0; m < 2; m++) {
                    const int row = sp * 64 + band2 * 32 + m * 16 + l4;
                    const __half* pp = &ph[row * LDPH + (c * 2 + kg) * 16 + 2 * lm];
                    aa[kg][m][0] = *(const unsigned*)&pp[0];
                    aa[kg][m][1] = *(const unsigned*)&pp[8 * LDPH];
                    aa[kg][m][2] = *(const unsigned*)&pp[8];
                    aa[kg][m][3] = *(const unsigned*)&pp[8 * LDPH + 8];
                }
#pragma unroll
            for (int t = 0; t < 16; t++) {
                const uint4 Bt = WOB[(cg2 * 16 + t) * 32 + lane];
#pragma unroll
                for (int kg = 0; kg < 2; kg++) {
                    const unsigned b0 = kg ? Bt.z : Bt.x;
                    const unsigned b1 = kg ? Bt.w : Bt.y;
                    mma16(facc[0][t], aa[kg][0][0], aa[kg][0][1], aa[kg][0][2], aa[kg][0][3], b0, b1);
                    mma16(facc[1][t], aa[kg][1][0], aa[kg][1][1], aa[kg][1][2], aa[kg][1][3], b0, b1);
                }
            }
        }

        // epilogue: +bo, row sumsq, norm, scale, store
        float ssA[2] = {0.f, 0.f}, ssB[2] = {0.f, 0.f};
#pragma unroll
        for (int m = 0; m < 2; m++)
#pragma unroll
            for (int t = 0; t < 16; t++) {
                const int col = cg2 * 128 + t * 8 + 2 * lm;
                const float2 b2 = *(const float2*)&sm[OFF_BG + col];
                facc[m][t][0] += b2.x; facc[m][t][1] += b2.y;
                facc[m][t][2] += b2.x; facc[m][t][3] += b2.y;
                ssA[m] += facc[m][t][0] * facc[m][t][0] + facc[m][t][1] * facc[m][t][1];
                ssB[m] += facc[m][t][2] * facc[m][t][2] + facc[m][t][3] * facc[m][t][3];
            }
#pragma unroll
        for (int m = 0; m < 2; m++) {
            ssA[m] += __shfl_xor_sync(0xffffffffu, ssA[m], 1);
            ssA[m] += __shfl_xor_sync(0xffffffffu, ssA[m], 2);
            ssB[m] += __shfl_xor_sync(0xffffffffu, ssB[m], 1);
            ssB[m] += __shfl_xor_sync(0xffffffffu, ssB[m], 2);
            if (lm == 0) {
                atomicAdd(&sm[OFF_N2 + band2 * 32 + m * 16 + l4], ssA[m]);
                atomicAdd(&sm[OFF_N2 + band2 * 32 + m * 16 + l4 + 8], ssB[m]);
            }
        }
        __syncthreads();
        if (tid < 64) {
            sm[OFF_RS + tid] = 22.627416997969522f / fmaxf(sqrtf(sm[OFF_N2 + tid]), 1e-12f);
            sm[OFF_N2 + tid] = 0.f;
        }
        __syncthreads();

#pragma unroll
        for (int m = 0; m < 2; m++) {
            const int rloc = band2 * 32 + m * 16 + l4;
            const float cA = sm[OFF_RS + rloc], cB = sm[OFF_RS + rloc + 8];
            const size_t gr = (Rbase + sp * 64 + rloc) * 512;
#pragma unroll
            for (int t = 0; t < 16; t++) {
                const int col = cg2 * 128 + t * 8 + 2 * lm;
                const float2 g2 = *(const float2*)&sm[OFF_BG + 512 + col];
                *(float2*)&out[gr + col] =
                    make_float2(facc[m][t][0] * cA * g2.x, facc[m][t][1] * cA * g2.y);
                *(float2*)&out[gr + 8 * 512 + col] =
                    make_float2(facc[m][t][2] * cB * g2.x, facc[m][t][3] * cB * g2.y);
            }
        }
    }
}

extern "C" void kernel_launch(void* const* d_in, const int* in_sizes, int n_in,
                              void* d_out, int out_size)
{
    const float* x   = (const float*)d_in[0];
    const float* ctx = (const float*)d_in[1];
    const float* Wq  = (const float*)d_in[2];
    const float* Wk  = (const float*)d_in[3];
    const float* Wv  = (const float*)d_in[4];
    const float* Wo  = (const float*)d_in[5];
    const float* bo  = (const float*)d_in[6];
    const float* g   = (const float*)d_in[7];
    float* out = (float*)d_out;

    const int B = in_sizes[0] / 512;   // 65536
    const size_t SMEM = (size_t)SMEM_FLOATS * sizeof(float);   // 223744 B

    lca_prep<<<1280, 256>>>(Wq, Wk, Wv, Wo);

    cudaFuncSetAttribute(lca_tc, cudaFuncAttributeMaxDynamicSharedMemorySize, (int)SMEM);
    lca_tc<<<B / ROWS, THREADS, SMEM>>>(x, ctx, bo, g, out);
}

// round 15
// speedup vs baseline: 1.8833x; 1.0344x over previous
#include <cuda_runtime.h>
#include <cuda_fp16.h>
#include <math.h>
#include <stdint.h>

#define THREADS 256
#define ROWS 128
#define LDA 40     // act smem row stride (32+8)
#define LDPH 136   // P/q half stride

// smem float offsets
#define OFF_PH  0        // q then P (half): 128*136 halves = 8704 floats
#define OFF_ACT 8704     // 5 x 5120 = 25600 (ends 34304)
#define OFF_W   34304    // 5 x 4096 = 20480 (ends 54784)
#define OFF_WO  8704     // phase C: 2 x 8192 = 16384 (overlays ACT region)
#define OFF_BG  54784    // bo 512 | g 512
#define OFF_N2  55808    // 64
#define OFF_RS  55872    // 64
#define SMEM_FLOATS 55936   // 223744 bytes

// frag-major fp16 weights: proj [kc][T16][lane][8h], Wo [c][T64][lane][8h]
__device__ __half WqH[16 * 4096];
__device__ __half WkH[24 * 4096];
__device__ __half WvH[24 * 4096];
__device__ __half WoH[4 * 16384];

__device__ __forceinline__ void mma16(float* d, unsigned a0, unsigned a1, unsigned a2,
                                      unsigned a3, unsigned b0, unsigned b1) {
    asm volatile(
        "mma.sync.aligned.m16n8k16.row.col.f32.f16.f16.f32 "
        "{%0,%1,%2,%3},{%4,%5,%6,%7},{%8,%9},{%0,%1,%2,%3};"
        : "+f"(d[0]), "+f"(d[1]), "+f"(d[2]), "+f"(d[3])
        : "r"(a0), "r"(a1), "r"(a2), "r"(a3), "r"(b0), "r"(b1));
}

__device__ __forceinline__ unsigned f2h(float lo, float hi) {
    __half2 h = __floats2half2_rn(lo, hi);
    return *(unsigned*)&h;
}

#define CP_COMMIT() asm volatile("cp.async.commit_group;")
#define CP_WAIT0()  asm volatile("cp.async.wait_group 0;")
#define CP_WAIT1()  asm volatile("cp.async.wait_group 1;")

__device__ __forceinline__ void cp16(float* smdst, const float* gsrc) {
    unsigned sa = (unsigned)__cvta_generic_to_shared(smdst);
    asm volatile("cp.async.cg.shared.global [%0], [%1], 16;" :: "r"(sa), "l"(gsrc));
}

// 128 rows x 32 floats -> [r*LDA + c]
__device__ __forceinline__ void act_cp(float* sm, int dstOff, const float* A,
                                       size_t rowBase, int gld, int kb, int tid) {
#pragma unroll
    for (int i = 0; i < 4; i++) {
        const int idx = tid + THREADS * i;
        const int r = idx >> 3, q = (idx & 7) * 4;
        cp16(&sm[dstOff + r * LDA + q], A + (rowBase + r) * (size_t)gld + kb + q);
    }
}
template <int NF>
__device__ __forceinline__ void w_cp(float* sm, int dstOff, const float* gsrc, int tid) {
#pragma unroll
    for (int i = tid * 4; i < NF; i += THREADS * 4)
        cp16(&sm[dstOff + i], gsrc + i);
}

// unified stream: chunks 0..15 = (x, Wq); 16..39 = (ctx, Wk+Wv). 5-stage ring.
__device__ __forceinline__ void issue_chunk(float* sm, int c, const float* x,
                                            const float* ctx, size_t Rbase, int tid) {
    const int st = c % 5;
    if (c < 16) {
        act_cp(sm, OFF_ACT + st * 5120, x, Rbase, 512, c * 32, tid);
        w_cp<2048>(sm, OFF_W + st * 4096, (const float*)WqH + c * 2048, tid);
    } else {
        const int cb = c - 16;
        act_cp(sm, OFF_ACT + st * 5120, ctx, Rbase, 768, cb * 32, tid);
        w_cp<2048>(sm, OFF_W + st * 4096, (const float*)WkH + cb * 2048, tid);
        w_cp<2048>(sm, OFF_W + st * 4096 + 2048, (const float*)WvH + cb * 2048, tid);
    }
    CP_COMMIT();
}

// ---------------- prep: fp32 row-major -> frag-major fp16 ----------------
__global__ void __launch_bounds__(256)
lca_prep(const float* __restrict__ Wq, const float* __restrict__ Wk,
         const float* __restrict__ Wv, const float* __restrict__ Wo)
{
    const int idx = blockIdx.x * 256 + threadIdx.x;   // < 327680
    if (idx < 65536) {
        int i = idx;
        int h = i & 7, lane = (i >> 3) & 31, T = (i >> 8) & 15, kc = i >> 12;
        int lm = lane & 3, l4 = lane >> 2;
        int k = kc * 32 + (h >> 1) * 8 + 2 * lm + (h & 1);
        WqH[i] = __float2half_rn(Wq[k * 128 + T * 8 + l4]);
    } else if (idx < 65536 + 98304) {
        int i = idx - 65536;
        int h = i & 7, lane = (i >> 3) & 31, T = (i >> 8) & 15, kc = i >> 12;
        int lm = lane & 3, l4 = lane >> 2;
        int k = kc * 32 + (h >> 1) * 8 + 2 * lm + (h & 1);
        WkH[i] = __float2half_rn(Wk[k * 128 + T * 8 + l4]);
    } else if (idx < 65536 + 2 * 98304) {
        int i = idx - 65536 - 98304;
        int h = i & 7, lane = (i >> 3) & 31, T = (i >> 8) & 15, kc = i >> 12;
        int lm = lane & 3, l4 = lane >> 2;
        int k = kc * 32 + (h >> 1) * 8 + 2 * lm + (h & 1);
        WvH[i] = __float2half_rn(Wv[k * 128 + T * 8 + l4]);
    } else {
        int i = idx - 65536 - 2 * 98304;
        int h = i & 7, lane = (i >> 3) & 31, T = (i >> 8) & 63, c = i >> 14;
        int lm = lane & 3, l4 = lane >> 2;
        int k = c * 32 + (h >> 1) * 8 + 2 * lm + (h & 1);
        WoH[i] = __float2half_rn(Wo[k * 512 + T * 8 + l4]);
    }
}

// A-fragment load + convert
#define LOAD_AFRAGS(AB)                                                          \
    unsigned aa[2][2][4];                                                        \
    {                                                                            \
        _Pragma("unroll")                                                        \
        for (int kg = 0; kg < 2; kg++)                                           \
            _Pragma("unroll")                                                    \
            for (int m = 0; m < 2; m++) {                                        \
                const float* p = &(AB)[(band * 32 + m * 16 + l4) * LDA + kg * 16 + 2 * lm]; \
                const float2 v0 = *(const float2*)p;                             \
                const float2 v1 = *(const float2*)(p + 8 * LDA);                 \
                const float2 v2 = *(const float2*)(p + 8);                       \
                const float2 v3 = *(const float2*)(p + 8 * LDA + 8);             \
                aa[kg][m][0] = f2h(v0.x, v0.y);                                  \
                aa[kg][m][1] = f2h(v1.x, v1.y);                                  \
                aa[kg][m][2] = f2h(v2.x, v2.y);                                  \
                aa[kg][m][3] = f2h(v3.x, v3.y);                                  \
            }                                                                    \
    }

// ---------------------------------- main ----------------------------------
__global__ void __launch_bounds__(THREADS, 1)
lca_tc(const float* __restrict__ x, const float* __restrict__ ctx,
       const float* __restrict__ bo, const float* __restrict__ g,
       float* __restrict__ out)
{
    extern __shared__ float sm[];
    __half* ph = (__half*)(sm + OFF_PH);
    const int tid  = threadIdx.x;
    const int lane = tid & 31;
    const int warp = tid >> 5;          // 0..7
    const int l4   = lane >> 2;
    const int lm   = lane & 3;
    const int band = warp >> 1;         // A/B: 4 bands x 32 rows
    const int cg   = warp & 1;          //      2 colgrps x 64 cols
    const size_t Rbase = (size_t)blockIdx.x * ROWS;

    for (int i = tid; i < 512; i += THREADS) {
        sm[OFF_BG + i]       = __ldg(&bo[i]);
        sm[OFF_BG + 512 + i] = __ldg(&g[i]);
    }
    if (tid < 64) sm[OFF_N2 + tid] = 0.f;

    // pipeline prologue: 3 chunks in flight
    issue_chunk(sm, 0, x, ctx, Rbase, tid);
    issue_chunk(sm, 1, x, ctx, Rbase, tid);
    issue_chunk(sm, 2, x, ctx, Rbase, tid);

    // ============== Phase A: q = x @ Wq (pairs, chunks 0..15) ==============
    {
        float qa[2][8][4];
#pragma unroll
        for (int m = 0; m < 2; m++)
#pragma unroll
            for (int t = 0; t < 8; t++)
#pragma unroll
                for (int j = 0; j < 4; j++) qa[m][t][j] = 0.f;

#pragma unroll 1
        for (int cp = 0; cp < 8; cp++) {
            const int c = 2 * cp;
            CP_WAIT1();
            __syncthreads();
#pragma unroll
            for (int sub = 0; sub < 2; sub++) {
                const int cc = c + sub;
                const float* AB = &sm[OFF_ACT + (cc % 5) * 5120];
                const uint4* WB = (const uint4*)&sm[OFF_W + (cc % 5) * 4096];
                LOAD_AFRAGS(AB)
                issue_chunk(sm, c + 3 + sub, x, ctx, Rbase, tid);   // <= 18
#pragma unroll
                for (int t = 0; t < 8; t++) {
                    const uint4 Bt = WB[(cg * 8 + t) * 32 + lane];
#pragma unroll
                    for (int kg = 0; kg < 2; kg++) {
                        const unsigned b0 = kg ? Bt.z : Bt.x;
                        const unsigned b1 = kg ? Bt.w : Bt.y;
                        mma16(qa[0][t], aa[kg][0][0], aa[kg][0][1], aa[kg][0][2], aa[kg][0][3], b0, b1);
                        mma16(qa[1][t], aa[kg][1][0], aa[kg][1][1], aa[kg][1][2], aa[kg][1][3], b0, b1);
                    }
                }
            }
        }

        // ===== softmax in registers; park q in smem (PH region) as half2 =====
        const float SCL = 0.17677669529663687f;   // 32^-0.5
#pragma unroll
        for (int m = 0; m < 2; m++) {
            const int rA = band * 32 + m * 16 + l4;
#pragma unroll
            for (int hh = 0; hh < 2; hh++) {
                float mxA = -1e30f, mxB = -1e30f;
#pragma unroll
                for (int tt = 0; tt < 4; tt++) {
                    const int t = 4 * hh + tt;
                    mxA = fmaxf(mxA, fmaxf(qa[m][t][0], qa[m][t][1]));
                    mxB = fmaxf(mxB, fmaxf(qa[m][t][2], qa[m][t][3]));
                }
                mxA = fmaxf(mxA, __shfl_xor_sync(0xffffffffu, mxA, 1));
                mxA = fmaxf(mxA, __shfl_xor_sync(0xffffffffu, mxA, 2));
                mxB = fmaxf(mxB, __shfl_xor_sync(0xffffffffu, mxB, 1));
                mxB = fmaxf(mxB, __shfl_xor_sync(0xffffffffu, mxB, 2));
                float sA = 0.f, sB = 0.f;
#pragma unroll
                for (int tt = 0; tt < 4; tt++) {
                    const int t = 4 * hh + tt;
                    qa[m][t][0] = __expf(qa[m][t][0] - mxA); sA += qa[m][t][0];
                    qa[m][t][1] = __expf(qa[m][t][1] - mxA); sA += qa[m][t][1];
                    qa[m][t][2] = __expf(qa[m][t][2] - mxB); sB += qa[m][t][2];
                    qa[m][t][3] = __expf(qa[m][t][3] - mxB); sB += qa[m][t][3];
                }
                sA += __shfl_xor_sync(0xffffffffu, sA, 1);
                sA += __shfl_xor_sync(0xffffffffu, sA, 2);
                sB += __shfl_xor_sync(0xffffffffu, sB, 1);
                sB += __shfl_xor_sync(0xffffffffu, sB, 2);
                const float iA = SCL / sA, iB = SCL / sB;
#pragma unroll
                for (int tt = 0; tt < 4; tt++) {
                    const int t = 4 * hh + tt;
                    const int col = (cg * 8 + t) * 8 + 2 * lm;
                    *(__half2*)&ph[rA * LDPH + col] =
                        __floats2half2_rn(qa[m][t][0] * iA, qa[m][t][1] * iA);
                    *(__half2*)&ph[(rA + 8) * LDPH + col] =
                        __floats2half2_rn(qa[m][t][2] * iB, qa[m][t][3] * iB);
                }
            }
        }
    }
    // q lives in smem (same-thread readback later) — no block sync needed

    // ===== Phase B: k=sigmoid(ctx@Wk), v=ctx@Wv (pairs, chunks 16..39) =====
    {
        float ka[2][8][4], va[2][8][4];
#pragma unroll
        for (int m = 0; m < 2; m++)
#pragma unroll
            for (int t = 0; t < 8; t++)
#pragma unroll
                for (int j = 0; j < 4; j++) { ka[m][t][j] = 0.f; va[m][t][j] = 0.f; }

#pragma unroll 1
        for (int cp = 8; cp < 20; cp++) {
            const int c = 2 * cp;
            if (c + 2 > 39) { CP_WAIT0(); } else { CP_WAIT1(); }
            __syncthreads();
#pragma unroll
            for (int sub = 0; sub < 2; sub++) {
                const int cc = c + sub;
                const float* AB = &sm[OFF_ACT + (cc % 5) * 5120];
                const uint4* KB = (const uint4*)&sm[OFF_W + (cc % 5) * 4096];
                const uint4* VB = (const uint4*)&sm[OFF_W + (cc % 5) * 4096 + 2048];
                LOAD_AFRAGS(AB)
                if (c + 3 + sub <= 39) issue_chunk(sm, c + 3 + sub, x, ctx, Rbase, tid);
#pragma unroll
                for (int t = 0; t < 8; t++) {
                    const uint4 BtK = KB[(cg * 8 + t) * 32 + lane];
                    const uint4 BtV = VB[(cg * 8 + t) * 32 + lane];
#pragma unroll
                    for (int kg = 0; kg < 2; kg++) {
                        unsigned b0 = kg ? BtK.z : BtK.x;
                        unsigned b1 = kg ? BtK.w : BtK.y;
                        mma16(ka[0][t], aa[kg][0][0], aa[kg][0][1], aa[kg][0][2], aa[kg][0][3], b0, b1);
                        mma16(ka[1][t], aa[kg][1][0], aa[kg][1][1], aa[kg][1][2], aa[kg][1][3], b0, b1);
                        b0 = kg ? BtV.z : BtV.x;
                        b1 = kg ? BtV.w : BtV.y;
                        mma16(va[0][t], aa[kg][0][0], aa[kg][0][1], aa[kg][0][2], aa[kg][0][3], b0, b1);
                        mma16(va[1][t], aa[kg][1][0], aa[kg][1][1], aa[kg][1][2], aa[kg][1][3], b0, b1);
                    }
                }
            }
        }

        // epilogue part 1: s = q . sigmoid(k), q read back from smem
        float d0v[2][2], d1v[2][2];
#pragma unroll
        for (int m = 0; m < 2; m++) {
            const int rA = band * 32 + m * 16 + l4;
            float d0[2] = {0.f, 0.f}, d1[2] = {0.f, 0.f};
#pragma unroll
            for (int t = 0; t < 8; t++) {
                const int hh = t >> 2;
                const int col = (cg * 8 + t) * 8 + 2 * lm;
                const float2 q1 = __half22float2(*(const __half2*)&ph[rA * LDPH + col]);
                const float2 q2 = __half22float2(*(const __half2*)&ph[(rA + 8) * LDPH + col]);
                d0[hh] += q1.x / (1.f + __expf(-ka[m][t][0])) + q1.y / (1.f + __expf(-ka[m][t][1]));
                d1[hh] += q2.x / (1.f + __expf(-ka[m][t][2])) + q2.y / (1.f + __expf(-ka[m][t][3]));
            }
#pragma unroll
            for (int hh = 0; hh < 2; hh++) {
                d0[hh] += __shfl_xor_sync(0xffffffffu, d0[hh], 1);
                d0[hh] += __shfl_xor_sync(0xffffffffu, d0[hh], 2);
                d1[hh] += __shfl_xor_sync(0xffffffffu, d1[hh], 1);
                d1[hh] += __shfl_xor_sync(0xffffffffu, d1[hh], 2);
                d0v[m][hh] = d0[hh]; d1v[m][hh] = d1[hh];
            }
        }
        __syncthreads();   // all act/W reads done; ACT region free for Wo

        w_cp<8192>(sm, OFF_WO, (const float*)WoH, tid);
        CP_COMMIT();

        // epilogue part 2: P = s*v as half2 (overwrites q region, same-thread)
#pragma unroll
        for (int m = 0; m < 2; m++) {
            const int rA = band * 32 + m * 16 + l4;
#pragma unroll
            for (int t = 0; t < 8; t++) {
                const int hh = t >> 2;
                const int col = (cg * 8 + t) * 8 + 2 * lm;
                *(__half2*)&ph[rA * LDPH + col] =
                    __floats2half2_rn(d0v[m][hh] * va[m][t][0], d0v[m][hh] * va[m][t][1]);
                *(__half2*)&ph[(rA + 8) * LDPH + col] =
                    __floats2half2_rn(d1v[m][hh] * va[m][t][2], d1v[m][hh] * va[m][t][3]);
            }
        }
    }

    // ===== Phase C: y = P @ Wo + bo, fused RMSNorm; 2 subpasses of 64 rows =====
    const int band2 = warp >> 2;   // 2 bands x 32 rows
    const int cg2   = warp & 3;    // 4 colgrps x 128 cols
#pragma unroll 1
    for (int sp = 0; sp < 2; sp++) {
        float facc[2][16][4];
#pragma unroll
        for (int m = 0; m < 2; m++)
#pragma unroll
            for (int t = 0; t < 16; t++)
#pragma unroll
                for (int j = 0; j < 4; j++) facc[m][t][j] = 0.f;

#pragma unroll 1
        for (int c = 0; c < 4; c++) {
            const int cb = c & 1;
            CP_WAIT0();
            __syncthreads();
            if (!(sp == 1 && c == 3)) {
                const int nc = (c + 1) & 3;
                w_cp<8192>(sm, OFF_WO + (cb ^ 1) * 8192, (const float*)WoH + nc * 8192, tid);
                CP_COMMIT();
            }
            const uint4* WOB = (const uint4*)&sm[OFF_WO + cb * 8192];

            unsigned aa[2][2][4];
#pragma unroll
            for (int kg = 0; kg < 2; kg++)
#pragma unroll
                for (int m = 0; m < 2; m++) {
                    const int row = sp * 64 + band2 * 32 + m * 16 + l4;
                    const __half* pp = &ph[row * LDPH + (c * 2 + kg) * 16 + 2 * lm];
                    aa[kg][m][0] = *(const unsigned*)&pp[0];
                    aa[kg][m][1] = *(const unsigned*)&pp[8 * LDPH];
                    aa[kg][m][2] = *(const unsigned*)&pp[8];
                    aa[kg][m][3] = *(const unsigned*)&pp[8 * LDPH + 8];
                }
#pragma unroll
            for (int t = 0; t < 16; t++) {
                const uint4 Bt = WOB[(cg2 * 16 + t) * 32 + lane];
#pragma unroll
                for (int kg = 0; kg < 2; kg++) {
                    const unsigned b0 = kg ? Bt.z : Bt.x;
                    const unsigned b1 = kg ? Bt.w : Bt.y;
                    mma16(facc[0][t], aa[kg][0][0], aa[kg][0][1], aa[kg][0][2], aa[kg][0][3], b0, b1);
                    mma16(facc[1][t], aa[kg][1][0], aa[kg][1][1], aa[kg][1][2], aa[kg][1][3], b0, b1);
                }
            }
        }

        // epilogue: +bo, row sumsq, norm, scale, store
        float ssA[2] = {0.f, 0.f}, ssB[2] = {0.f, 0.f};
#pragma unroll
        for (int m = 0; m < 2; m++)
#pragma unroll
            for (int t = 0; t < 16; t++) {
                const int col = cg2 * 128 + t * 8 + 2 * lm;
                const float2 b2 = *(const float2*)&sm[OFF_BG + col];
                facc[m][t][0] += b2.x; facc[m][t][1] += b2.y;
                facc[m][t][2] += b2.x; facc[m][t][3] += b2.y;
                ssA[m] += facc[m][t][0] * facc[m][t][0] + facc[m][t][1] * facc[m][t][1];
                ssB[m] += facc[m][t][2] * facc[m][t][2] + facc[m][t][3] * facc[m][t][3];
            }
#pragma unroll
        for (int m = 0; m < 2; m++) {
            ssA[m] += __shfl_xor_sync(0xffffffffu, ssA[m], 1);
            ssA[m] += __shfl_xor_sync(0xffffffffu, ssA[m], 2);
            ssB[m] += __shfl_xor_sync(0xffffffffu, ssB[m], 1);
            ssB[m] += __shfl_xor_sync(0xffffffffu, ssB[m], 2);
            if (lm == 0) {
                atomicAdd(&sm[OFF_N2 + band2 * 32 + m * 16 + l4], ssA[m]);
                atomicAdd(&sm[OFF_N2 + band2 * 32 + m * 16 + l4 + 8], ssB[m]);
            }
        }
        __syncthreads();
        if (tid < 64) {
            sm[OFF_RS + tid] = 22.627416997969522f / fmaxf(sqrtf(sm[OFF_N2 + tid]), 1e-12f);
            sm[OFF_N2 + tid] = 0.f;
        }
        __syncthreads();

#pragma unroll
        for (int m = 0; m < 2; m++) {
            const int rloc = band2 * 32 + m * 16 + l4;
            const float cA = sm[OFF_RS + rloc], cB = sm[OFF_RS + rloc + 8];
            const size_t gr = (Rbase + sp * 64 + rloc) * 512;
#pragma unroll
            for (int t = 0; t < 16; t++) {
                const int col = cg2 * 128 + t * 8 + 2 * lm;
                const float2 g2 = *(const float2*)&sm[OFF_BG + 512 + col];
                *(float2*)&out[gr + col] =
                    make_float2(facc[m][t][0] * cA * g2.x, facc[m][t][1] * cA * g2.y);
                *(float2*)&out[gr + 8 * 512 + col] =
                    make_float2(facc[m][t][2] * cB * g2.x, facc[m][t][3] * cB * g2.y);
            }
        }
    }
}

extern "C" void kernel_launch(void* const* d_in, const int* in_sizes, int n_in,
                              void* d_out, int out_size)
{
    const float* x   = (const float*)d_in[0];
    const float* ctx = (const float*)d_in[1];
    const float* Wq  = (const float*)d_in[2];
    const float* Wk  = (const float*)d_in[3];
    const float* Wv  = (const float*)d_in[4];
    const float* Wo  = (const float*)d_in[5];
    const float* bo  = (const float*)d_in[6];
    const float* g   = (const float*)d_in[7];
    float* out = (float*)d_out;

    const int B = in_sizes[0] / 512;   // 65536
    const size_t SMEM = (size_t)SMEM_FLOATS * sizeof(float);   // 223744 B

    lca_prep<<<1280, 256>>>(Wq, Wk, Wv, Wo);

    cudaFuncSetAttribute(lca_tc, cudaFuncAttributeMaxDynamicSharedMemorySize, (int)SMEM);
    lca_tc<<<B / ROWS, THREADS, SMEM>>>(x, ctx, bo, g, out);
}